// round 13
// baseline (speedup 1.0000x reference)
#include <cuda_runtime.h>
#include <cuda_bf16.h>
#include <math.h>
#include <stdint.h>

// ---------------- problem constants ----------------
constexpr int Tt   = 12;
constexpr int Nn   = 30000;
constexpr int Ee   = 480000;
constexpr int FIN  = 128;
constexpr int H1C  = 256;
constexpr int H2C  = 128;
constexpr int RAWC = 20;
constexpr int HID  = 256;
constexpr int OUTC = 64;
constexpr int DSEQ = H2C + RAWC;   // 148
constexpr int DSEQP= 160;          // padded (multiple of 32)
constexpr int G4   = 4 * HID;      // 1024
constexpr int ASTR = Tt * HID;     // 3072
constexpr size_t NT = (size_t)Nn * Tt;  // 360000

// weight split buffer offsets (elements)
constexpr size_t OFF_W1T  = 0;         // [256,128]
constexpr size_t OFF_W2T  = 32768;     // [128,256]
constexpr size_t OFF_WIH0 = 65536;     // [1024,160]
constexpr size_t OFF_WHH0 = 229376;    // [1024,256]
constexpr size_t OFF_WIH1 = 491520;    // [1024,256]
constexpr size_t OFF_WHH1 = 753664;    // [1024,256]
constexpr size_t OFF_FCNT = 1015808;   // [128,256]
constexpr size_t WSPLIT_SZ= 1048576;

// ---------------- scratch ----------------
__device__ float g_bufX[NT * 256];        // agg nodes -> support2
__device__ float g_seq [NT * DSEQ];
__device__ float g_xg  [NT * (size_t)G4];
__device__ float g_c   [(size_t)Nn * HID];
__device__ float g_z   [(size_t)Nn * 128];
__device__ __nv_bfloat16 g_ahi[NT * 256]; // agg split -> hseq0 chain -> hseq1 chain
__device__ __nv_bfloat16 g_alo[NT * 256];
__device__ __nv_bfloat16 g_bhi[NT * 256]; // x split -> seq split
__device__ __nv_bfloat16 g_blo[NT * 256];
__device__ __nv_bfloat16 g_phi[(size_t)Nn * HID];
__device__ __nv_bfloat16 g_plo[(size_t)Nn * HID];
__device__ __nv_bfloat16 g_whi[WSPLIT_SZ];
__device__ __nv_bfloat16 g_wlo[WSPLIT_SZ];

// ---------------- helpers ----------------
__device__ __forceinline__ uint32_t sptr(const void* p) {
    return (uint32_t)__cvta_generic_to_shared(p);
}
__device__ __forceinline__ void ldsm4(uint32_t* r, uint32_t a) {
    asm volatile("ldmatrix.sync.aligned.m8n8.x4.shared.b16 {%0,%1,%2,%3}, [%4];"
                 : "=r"(r[0]), "=r"(r[1]), "=r"(r[2]), "=r"(r[3]) : "r"(a));
}
__device__ __forceinline__ void ldsm2(uint32_t* r, uint32_t a) {
    asm volatile("ldmatrix.sync.aligned.m8n8.x2.shared.b16 {%0,%1}, [%2];"
                 : "=r"(r[0]), "=r"(r[1]) : "r"(a));
}
__device__ __forceinline__ void mma_bf16(float* c, const uint32_t* a, const uint32_t* b) {
    asm volatile("mma.sync.aligned.m16n8k16.row.col.f32.bf16.bf16.f32 "
                 "{%0,%1,%2,%3}, {%4,%5,%6,%7}, {%8,%9}, {%0,%1,%2,%3};"
                 : "+f"(c[0]), "+f"(c[1]), "+f"(c[2]), "+f"(c[3])
                 : "r"(a[0]), "r"(a[1]), "r"(a[2]), "r"(a[3]), "r"(b[0]), "r"(b[1]));
}
__device__ __forceinline__ void cpasync16(void* dst, const void* src, bool pred) {
    int sz = pred ? 16 : 0;
    asm volatile("cp.async.cg.shared.global [%0], [%1], 16, %2;"
                 :: "r"(sptr(dst)), "l"(src), "r"(sz));
}
__device__ __forceinline__ void red4(float* addr, float x, float y, float z, float w) {
    asm volatile("red.global.add.v4.f32 [%0], {%1,%2,%3,%4};"
                 :: "l"(addr), "f"(x), "f"(y), "f"(z), "f"(w) : "memory");
}
__device__ __forceinline__ float sigmoidf_(float x) { return 1.f / (1.f + expf(-x)); }

// =====================================================================
// 256x128 block GEMM, 8 warps, warp tile 64x64, 3-pass bf16 split.
// A:[M,lda] split row-major; B:[Nc,lda] split (B^T). Nc % 128 == 0.
// =====================================================================
#define GP 40
#define AELTS (256 * GP)              // 10240
#define BELTS (128 * GP)              // 5120
#define STG_E (2 * AELTS + 2 * BELTS) // 30720 elts per stage
#define G2_SMEM (2 * STG_E * 2)       // 122880 bytes

__global__ void __launch_bounds__(256, 1) gemm256(
    const __nv_bfloat16* __restrict__ Ahi, const __nv_bfloat16* __restrict__ Alo,
    const __nv_bfloat16* __restrict__ Bhi, const __nv_bfloat16* __restrict__ Blo,
    float* __restrict__ C, __nv_bfloat16* __restrict__ Chi, __nv_bfloat16* __restrict__ Clo,
    const float* __restrict__ bias,
    int M, int lda, int Nc, int relu_c, int out_split)
{
    extern __shared__ __nv_bfloat16 sm[];

    const int tid  = threadIdx.x;
    const int lane = tid & 31;
    const int warp = tid >> 5;
    const int warp_m = (warp >> 1) << 6;  // 0,64,128,192
    const int warp_n = (warp & 1) << 6;   // 0,64
    const int brow = blockIdx.y * 256;
    const int bcol = blockIdx.x * 128;

    float acc[4][8][4];
#pragma unroll
    for (int i = 0; i < 4; i++)
#pragma unroll
        for (int j = 0; j < 8; j++)
#pragma unroll
            for (int v = 0; v < 4; v++) acc[i][j][v] = 0.f;

    // loaders
    const int a_gr = brow + tid;
    const bool okA = (a_gr < M);
    const int a_grc = okA ? a_gr : 0;
    const int b_gn = bcol + (tid >> 1);
    const int b_kc = (tid & 1) << 4;

    // ldsm addressing
    const int a_lrow = (lane & 7) + ((lane >> 3) & 1) * 8;
    const int a_lcol = (lane >> 4) * 8;
    const int b_row  = ((lane >> 4) & 1) * 8 + (lane & 7);
    const int b_col  = ((lane >> 3) & 1) * 8;

    auto load_stage = [&](int s, int k0) {
        __nv_bfloat16* base = sm + s * STG_E;
        size_t aoff = (size_t)a_grc * lda + k0;
        int aso = tid * GP;
#pragma unroll
        for (int q = 0; q < 4; q++) {
            cpasync16(base + aso + 8 * q,         Ahi + aoff + 8 * q, okA);
            cpasync16(base + AELTS + aso + 8 * q, Alo + aoff + 8 * q, okA);
        }
        size_t boff = (size_t)b_gn * lda + k0 + b_kc;
        int bso = (tid >> 1) * GP + b_kc;
#pragma unroll
        for (int q = 0; q < 2; q++) {
            cpasync16(base + 2 * AELTS + bso + 8 * q,         Bhi + boff + 8 * q, true);
            cpasync16(base + 2 * AELTS + BELTS + bso + 8 * q, Blo + boff + 8 * q, true);
        }
        asm volatile("cp.async.commit_group;" ::: "memory");
    };

    auto compute = [&](int s) {
        __nv_bfloat16* As_hi = sm + s * STG_E;
        __nv_bfloat16* As_lo = As_hi + AELTS;
        __nv_bfloat16* Bs_hi = As_hi + 2 * AELTS;
        __nv_bfloat16* Bs_lo = Bs_hi + BELTS;
#pragma unroll
        for (int st = 0; st < 2; st++) {
            int kb = st * 16;
            uint32_t A[4][4], B[4][4];
            // pass 1: Ahi x Bhi
#pragma unroll
            for (int mi = 0; mi < 4; mi++)
                ldsm4(A[mi], sptr(&As_hi[(warp_m + mi * 16 + a_lrow) * GP + kb + a_lcol]));
#pragma unroll
            for (int g = 0; g < 4; g++)
                ldsm4(B[g], sptr(&Bs_hi[(warp_n + g * 16 + b_row) * GP + kb + b_col]));
#pragma unroll
            for (int mi = 0; mi < 4; mi++)
#pragma unroll
                for (int g = 0; g < 4; g++) {
                    mma_bf16(acc[mi][2 * g],     A[mi], &B[g][0]);
                    mma_bf16(acc[mi][2 * g + 1], A[mi], &B[g][2]);
                }
            // pass 2: Ahi x Blo
#pragma unroll
            for (int g = 0; g < 4; g++)
                ldsm4(B[g], sptr(&Bs_lo[(warp_n + g * 16 + b_row) * GP + kb + b_col]));
#pragma unroll
            for (int mi = 0; mi < 4; mi++)
#pragma unroll
                for (int g = 0; g < 4; g++) {
                    mma_bf16(acc[mi][2 * g],     A[mi], &B[g][0]);
                    mma_bf16(acc[mi][2 * g + 1], A[mi], &B[g][2]);
                }
            // pass 3: Alo x Bhi (reload both)
#pragma unroll
            for (int mi = 0; mi < 4; mi++)
                ldsm4(A[mi], sptr(&As_lo[(warp_m + mi * 16 + a_lrow) * GP + kb + a_lcol]));
#pragma unroll
            for (int g = 0; g < 4; g++)
                ldsm4(B[g], sptr(&Bs_hi[(warp_n + g * 16 + b_row) * GP + kb + b_col]));
#pragma unroll
            for (int mi = 0; mi < 4; mi++)
#pragma unroll
                for (int g = 0; g < 4; g++) {
                    mma_bf16(acc[mi][2 * g],     A[mi], &B[g][0]);
                    mma_bf16(acc[mi][2 * g + 1], A[mi], &B[g][2]);
                }
        }
    };

    const int KT = lda >> 5;
    load_stage(0, 0);
    for (int kt = 0; kt < KT; kt++) {
        if (kt + 1 < KT) {
            load_stage((kt + 1) & 1, (kt + 1) << 5);
            asm volatile("cp.async.wait_group 1;" ::: "memory");
        } else {
            asm volatile("cp.async.wait_group 0;" ::: "memory");
        }
        __syncthreads();
        compute(kt & 1);
        __syncthreads();
    }

    // epilogue
#pragma unroll
    for (int mi = 0; mi < 4; mi++) {
#pragma unroll
        for (int ni = 0; ni < 8; ni++) {
            int n0 = bcol + warp_n + ni * 8 + (lane & 3) * 2;
            float bx = bias ? bias[n0] : 0.f;
            float by = bias ? bias[n0 + 1] : 0.f;
            int m0 = brow + warp_m + mi * 16 + (lane >> 2);
#pragma unroll
            for (int h = 0; h < 2; h++) {
                int m = m0 + h * 8;
                if (m >= M) continue;
                float vx = acc[mi][ni][h * 2 + 0] + bx;
                float vy = acc[mi][ni][h * 2 + 1] + by;
                if (relu_c) { vx = fmaxf(vx, 0.f); vy = fmaxf(vy, 0.f); }
                if (out_split) {
                    __nv_bfloat16 h0 = __float2bfloat16(vx);
                    __nv_bfloat16 h1 = __float2bfloat16(vy);
                    __nv_bfloat162 hv; hv.x = h0; hv.y = h1;
                    __nv_bfloat162 lv;
                    lv.x = __float2bfloat16(vx - __bfloat162float(h0));
                    lv.y = __float2bfloat16(vy - __bfloat162float(h1));
                    *reinterpret_cast<__nv_bfloat162*>(&Chi[(size_t)m * Nc + n0]) = hv;
                    *reinterpret_cast<__nv_bfloat162*>(&Clo[(size_t)m * Nc + n0]) = lv;
                } else {
                    float2 v; v.x = vx; v.y = vy;
                    *reinterpret_cast<float2*>(&C[(size_t)m * Nc + n0]) = v;
                }
            }
        }
    }
}

// =====================================================================
// Fused LSTM step (R6, proven): gates = h_{t-1}@Whh^T (+xg_t+bhh), pointwise.
// =====================================================================
#define PITCH 40
#define BUFE  (128 * PITCH)
#define SHBYTES (2 * 4 * BUFE * 2)   // 81920

__global__ void __launch_bounds__(256, 2) lstm_step_kernel(
    const __nv_bfloat16* __restrict__ Ahi, const __nv_bfloat16* __restrict__ Alo,
    const __nv_bfloat16* __restrict__ Bhi, const __nv_bfloat16* __restrict__ Blo,
    const float* __restrict__ xg, const float* __restrict__ bhh,
    float* __restrict__ cst,
    __nv_bfloat16* __restrict__ Ohi, __nv_bfloat16* __restrict__ Olo,
    int M, int t)
{
    extern __shared__ __nv_bfloat16 smem2[];

    const int tid  = threadIdx.x;
    const int lane = tid & 31;
    const int warp = tid >> 5;
    const int warp_m = (warp >> 2) << 6;
    const int warp_n = (warp & 3) << 5;
    const int brow = blockIdx.y * 128;
    const int hc0  = blockIdx.x * 32;

    float acc[4][4][4];
#pragma unroll
    for (int i = 0; i < 4; i++)
#pragma unroll
        for (int j = 0; j < 4; j++)
#pragma unroll
            for (int v = 0; v < 4; v++) acc[i][j][v] = 0.f;

    const int l_row = tid >> 1;
    const int l_kc  = (tid & 1) << 4;
    const int gr  = brow + l_row;
    const bool okA = (gr < M);
    const int grc = okA ? gr : 0;
    const int b_gate = l_row >> 5;
    const int b_idx  = l_row & 31;
    const int gBrow  = b_gate * 256 + hc0 + b_idx;

    const int a_lrow = (lane & 7) + ((lane >> 3) & 1) * 8;
    const int a_lcol = (lane >> 4) * 8;
    const int b_lrow = lane & 7;
    const int b_lcol = ((lane >> 3) & 1) * 8;

    auto load_stage = [&](int s, int k0) {
        __nv_bfloat16* base = smem2 + s * 4 * BUFE;
        size_t aoff = (size_t)grc * ASTR + k0 + l_kc;
        size_t boff = (size_t)gBrow * HID + k0 + l_kc;
        int so = l_row * PITCH + l_kc;
        cpasync16(base + 0 * BUFE + so,     Ahi + aoff,     okA);
        cpasync16(base + 0 * BUFE + so + 8, Ahi + aoff + 8, okA);
        cpasync16(base + 1 * BUFE + so,     Alo + aoff,     okA);
        cpasync16(base + 1 * BUFE + so + 8, Alo + aoff + 8, okA);
        cpasync16(base + 2 * BUFE + so,     Bhi + boff,     true);
        cpasync16(base + 2 * BUFE + so + 8, Bhi + boff + 8, true);
        cpasync16(base + 3 * BUFE + so,     Blo + boff,     true);
        cpasync16(base + 3 * BUFE + so + 8, Blo + boff + 8, true);
    };

    auto compute = [&](int s) {
        __nv_bfloat16* As_hi = smem2 + (s * 4 + 0) * BUFE;
        __nv_bfloat16* As_lo = smem2 + (s * 4 + 1) * BUFE;
        __nv_bfloat16* Bs_hi = smem2 + (s * 4 + 2) * BUFE;
        __nv_bfloat16* Bs_lo = smem2 + (s * 4 + 3) * BUFE;
#pragma unroll
        for (int st = 0; st < 2; st++) {
            int kb = st * 16;
            uint32_t A[4][4], Bh[4][2], Bl[4][2];
#pragma unroll
            for (int mi = 0; mi < 4; mi++)
                ldsm4(A[mi], sptr(&As_hi[(warp_m + mi * 16 + a_lrow) * PITCH + kb + a_lcol]));
#pragma unroll
            for (int ni = 0; ni < 4; ni++)
                ldsm2(Bh[ni], sptr(&Bs_hi[(warp_n + ni * 8 + b_lrow) * PITCH + kb + b_lcol]));
#pragma unroll
            for (int mi = 0; mi < 4; mi++)
#pragma unroll
                for (int ni = 0; ni < 4; ni++) mma_bf16(acc[mi][ni], A[mi], Bh[ni]);
#pragma unroll
            for (int ni = 0; ni < 4; ni++)
                ldsm2(Bl[ni], sptr(&Bs_lo[(warp_n + ni * 8 + b_lrow) * PITCH + kb + b_lcol]));
#pragma unroll
            for (int mi = 0; mi < 4; mi++)
#pragma unroll
                for (int ni = 0; ni < 4; ni++) mma_bf16(acc[mi][ni], A[mi], Bl[ni]);
#pragma unroll
            for (int mi = 0; mi < 4; mi++)
                ldsm4(A[mi], sptr(&As_lo[(warp_m + mi * 16 + a_lrow) * PITCH + kb + a_lcol]));
#pragma unroll
            for (int mi = 0; mi < 4; mi++)
#pragma unroll
                for (int ni = 0; ni < 4; ni++) mma_bf16(acc[mi][ni], A[mi], Bh[ni]);
        }
    };

    const int KT = HID >> 5;
    load_stage(0, 0);
    asm volatile("cp.async.commit_group;" ::: "memory");
    for (int kt = 0; kt < KT; kt++) {
        if (kt + 1 < KT) {
            load_stage((kt + 1) & 1, (kt + 1) << 5);
            asm volatile("cp.async.commit_group;" ::: "memory");
            asm volatile("cp.async.wait_group 1;" ::: "memory");
        } else {
            asm volatile("cp.async.wait_group 0;" ::: "memory");
        }
        __syncthreads();
        compute(kt & 1);
        __syncthreads();
    }

    float* gsm = reinterpret_cast<float*>(smem2);
#pragma unroll
    for (int mi = 0; mi < 4; mi++) {
#pragma unroll
        for (int ni = 0; ni < 4; ni++) {
            int lc = warp_n + ni * 8 + (lane & 3) * 2;
            int r0 = warp_m + mi * 16 + (lane >> 2);
#pragma unroll
            for (int h = 0; h < 2; h++) {
                int r = r0 + h * 8;
                gsm[r * 132 + lc]     = acc[mi][ni][h * 2 + 0];
                gsm[r * 132 + lc + 1] = acc[mi][ni][h * 2 + 1];
            }
        }
    }
    __syncthreads();

    for (int idx = tid; idx < 128 * 32; idx += 256) {
        int row = idx >> 5;
        int col = idx & 31;
        int m = brow + row;
        if (m >= M) continue;
        int hc = hc0 + col;
        size_t xr = ((size_t)m * Tt + t) * G4;
        float gi = gsm[row * 132 +  0 + col] + xg[xr + hc]       + bhh[hc];
        float gf = gsm[row * 132 + 32 + col] + xg[xr + 256 + hc] + bhh[256 + hc];
        float gg = gsm[row * 132 + 64 + col] + xg[xr + 512 + hc] + bhh[512 + hc];
        float go = gsm[row * 132 + 96 + col] + xg[xr + 768 + hc] + bhh[768 + hc];
        size_t ci = (size_t)m * HID + hc;
        float cn = sigmoidf_(gf) * cst[ci] + sigmoidf_(gi) * tanhf(gg);
        float hn = sigmoidf_(go) * tanhf(cn);
        cst[ci] = cn;
        size_t ho = (size_t)m * ASTR + hc;
        __nv_bfloat16 hh = __float2bfloat16(hn);
        Ohi[ho] = hh;
        Olo[ho] = __float2bfloat16(hn - __bfloat162float(hh));
    }
}

__global__ void lstm_init_kernel(const float* __restrict__ xg, const float* __restrict__ bhh,
                                 float* __restrict__ cst,
                                 __nv_bfloat16* __restrict__ Ohi, __nv_bfloat16* __restrict__ Olo)
{
    size_t idx = (size_t)blockIdx.x * blockDim.x + threadIdx.x;
    if (idx >= (size_t)Nn * HID) return;
    size_t n = idx >> 8;
    int hc = (int)(idx & 255);
    size_t xr = n * Tt * (size_t)G4;
    float gi = xg[xr + hc]       + bhh[hc];
    float gg = xg[xr + 512 + hc] + bhh[512 + hc];
    float go = xg[xr + 768 + hc] + bhh[768 + hc];
    float cn = sigmoidf_(gi) * tanhf(gg);
    float hn = sigmoidf_(go) * tanhf(cn);
    cst[idx] = cn;
    size_t ho = n * ASTR + hc;
    __nv_bfloat16 hh = __float2bfloat16(hn);
    Ohi[ho] = hh;
    Olo[ho] = __float2bfloat16(hn - __bfloat162float(hh));
}

// ---------------- split / init kernels ----------------
__global__ void split_rows(const float* __restrict__ src,
                           __nv_bfloat16* __restrict__ hi, __nv_bfloat16* __restrict__ lo,
                           long long R, int C, int Cp, int relu)
{
    long long total = R * (Cp >> 2);
    long long stride = (long long)gridDim.x * blockDim.x;
    int gpr = Cp >> 2;
    for (long long g = (long long)blockIdx.x * blockDim.x + threadIdx.x; g < total; g += stride) {
        int gp = (int)(g % gpr);
        long long r = g / gpr;
        int c = gp << 2;
        float4 v = make_float4(0.f, 0.f, 0.f, 0.f);
        if (c + 3 < C) v = *reinterpret_cast<const float4*>(&src[r * C + c]);
        else if (c < C) {
            float tmp[4] = {0.f, 0.f, 0.f, 0.f};
            for (int e = 0; e < 4 && c + e < C; e++) tmp[e] = src[r * C + c + e];
            v.x = tmp[0]; v.y = tmp[1]; v.z = tmp[2]; v.w = tmp[3];
        }
        if (relu) {
            v.x = fmaxf(v.x, 0.f); v.y = fmaxf(v.y, 0.f);
            v.z = fmaxf(v.z, 0.f); v.w = fmaxf(v.w, 0.f);
        }
        float vv[4] = {v.x, v.y, v.z, v.w};
        __nv_bfloat16 h4[4], l4[4];
#pragma unroll
        for (int e = 0; e < 4; e++) {
            h4[e] = __float2bfloat16(vv[e]);
            l4[e] = __float2bfloat16(vv[e] - __bfloat162float(h4[e]));
        }
        *reinterpret_cast<uint2*>(&hi[r * Cp + c]) = *reinterpret_cast<uint2*>(h4);
        *reinterpret_cast<uint2*>(&lo[r * Cp + c]) = *reinterpret_cast<uint2*>(l4);
    }
}

// all weight splits in one launch
__global__ void split_weights_all(const float* __restrict__ W1, const float* __restrict__ W2,
                                  const float* __restrict__ Wih0, const float* __restrict__ Whh0,
                                  const float* __restrict__ Wih1, const float* __restrict__ Whh1,
                                  const float* __restrict__ fcn_w,
                                  __nv_bfloat16* __restrict__ whi, __nv_bfloat16* __restrict__ wlo)
{
    int stride = gridDim.x * blockDim.x;
    for (int i = blockIdx.x * blockDim.x + threadIdx.x; i < (int)WSPLIT_SZ; i += stride) {
        float v;
        if (i < 32768) {                       // W1T [256,128] <- W1[128,256]
            int n = i >> 7, k = i & 127; v = W1[k * 256 + n];
        } else if (i < 65536) {                // W2T [128,256] <- W2[256,128]
            int j = i - 32768; int n = j >> 8, k = j & 255; v = W2[k * 128 + n];
        } else if (i < 229376) {               // WIH0 [1024,160] pad from [1024,148]
            int j = i - 65536; int r = j / DSEQP, c = j % DSEQP;
            v = (c < DSEQ) ? Wih0[r * DSEQ + c] : 0.f;
        } else if (i < 491520) {               // WHH0 [1024,256]
            v = Whh0[i - 229376];
        } else if (i < 753664) {               // WIH1 [1024,256]
            v = Wih1[i - 491520];
        } else if (i < 1015808) {              // WHH1 [1024,256]
            v = Whh1[i - 753664];
        } else {                               // FCNT [128,256] <- fcn_w[256,128]
            int j = i - 1015808; int n = j >> 8, k = j & 255; v = fcn_w[k * 128 + n];
        }
        __nv_bfloat16 h = __float2bfloat16(v);
        whi[i] = h;
        wlo[i] = __float2bfloat16(v - __bfloat162float(h));
    }
}

__global__ void zero_f4(float4* __restrict__ p, size_t n4)
{
    size_t stride = (size_t)gridDim.x * blockDim.x;
    for (size_t i = (size_t)blockIdx.x * blockDim.x + threadIdx.x; i < n4; i += stride)
        p[i] = make_float4(0.f, 0.f, 0.f, 0.f);
}

__global__ void init_seq(float* __restrict__ seq, const float* __restrict__ b2,
                         const float* __restrict__ raw, size_t total)
{
    size_t stride = (size_t)gridDim.x * blockDim.x;
    for (size_t i = (size_t)blockIdx.x * blockDim.x + threadIdx.x; i < total; i += stride) {
        int c = (int)(i % DSEQ);
        size_t nt = i / DSEQ;
        int t = (int)(nt % Tt);
        size_t n = nt / Tt;
        seq[i] = (c < H2C) ? b2[c]
                           : raw[(size_t)t * Nn * RAWC + n * RAWC + (c - H2C)];
    }
}

// ---------------- fp32 fallback GEMM (final out gemm, Nc=64) ----------------
template<int BM, int BN, int BK, int TM, int TN>
__global__ void sgemm_kernel(const float* __restrict__ A, const float* __restrict__ B,
                             float* __restrict__ C, const float* __restrict__ bias,
                             int M, int K, int Nc)
{
    __shared__ float As[BK][BM];
    __shared__ float Bs[BK][BN];
    const int tid = threadIdx.x;
    const int brow = blockIdx.y * BM;
    const int bcol = blockIdx.x * BN;
    const int trow = (tid / (BN / TN)) * TM;
    const int tcol = (tid % (BN / TN)) * TN;

    float acc[TM][TN];
#pragma unroll
    for (int i = 0; i < TM; i++)
#pragma unroll
        for (int j = 0; j < TN; j++) acc[i][j] = 0.f;

    for (int k0 = 0; k0 < K; k0 += BK) {
#pragma unroll
        for (int i = 0; i < (BM * BK) / 256; i++) {
            int l = tid + i * 256;
            int m = l / BK, k = l % BK;
            int gr = brow + m, gk = k0 + k;
            As[k][m] = (gr < M && gk < K) ? A[(size_t)gr * K + gk] : 0.f;
        }
#pragma unroll
        for (int i = 0; i < (BK * BN) / 256; i++) {
            int l = tid + i * 256;
            int k = l / BN, n = l % BN;
            int gk = k0 + k, gn = bcol + n;
            Bs[k][n] = (gk < K && gn < Nc) ? B[(size_t)gk * Nc + gn] : 0.f;
        }
        __syncthreads();
#pragma unroll
        for (int k = 0; k < BK; k++) {
            float ar[TM], br[TN];
#pragma unroll
            for (int i = 0; i < TM; i++) ar[i] = As[k][trow + i];
#pragma unroll
            for (int j = 0; j < TN; j++) br[j] = Bs[k][tcol + j];
#pragma unroll
            for (int i = 0; i < TM; i++)
#pragma unroll
                for (int j = 0; j < TN; j++) acc[i][j] = fmaf(ar[i], br[j], acc[i][j]);
        }
        __syncthreads();
    }
#pragma unroll
    for (int i = 0; i < TM; i++) {
        int gr = brow + trow + i;
        if (gr >= M) continue;
#pragma unroll
        for (int j = 0; j < TN; j++) {
            int gn = bcol + tcol + j;
            if (gn >= Nc) continue;
            float v = acc[i][j];
            if (bias) v += bias[gn];
            C[(size_t)gr * Nc + gn] = v;
        }
    }
}

// ---------------- SpMM scatter (128-col) ----------------
__global__ void spmm_scatter128(const float* __restrict__ src,
                                const int* __restrict__ erow, const int* __restrict__ ecol,
                                const float* __restrict__ ew,
                                float* __restrict__ dst,
                                int dst_ld, int dst_layout)
{
    long long warp = ((long long)blockIdx.x * blockDim.x + threadIdx.x) >> 5;
    int lane = threadIdx.x & 31;
    if (warp >= (long long)Tt * Ee) return;
    int t = (int)(warp / Ee);
    int e = (int)(warp % Ee);
    size_t eoff = (size_t)t * Ee + e;
    int r = erow[eoff];
    int c = ecol[eoff];
    float w = ew[eoff];
    const float* s = src + ((size_t)t * Nn + c) * 128;
    size_t doff = (dst_layout == 0) ? ((size_t)t * Nn + r) * (size_t)dst_ld
                                    : ((size_t)r * Tt + t) * (size_t)dst_ld;
    float* d = dst + doff;
    int j = lane << 2;
    float4 v = *reinterpret_cast<const float4*>(&s[j]);
    red4(&d[j], w * v.x, w * v.y, w * v.z, w * v.w);
}

// ---------------- attention pooling (reads split hseq chain) ----------------
__global__ void attention_pool(const __nv_bfloat16* __restrict__ hhi,
                               const __nv_bfloat16* __restrict__ hlo,
                               const float* __restrict__ att_w,
                               const float* __restrict__ att_b,
                               __nv_bfloat16* __restrict__ phi,
                               __nv_bfloat16* __restrict__ plo)
{
    __shared__ float hs[Tt * HID];
    __shared__ float aw[HID];
    __shared__ float red[HID];
    __shared__ float sc[Tt];
    int n = blockIdx.x;
    int tid = threadIdx.x;
    size_t base = (size_t)n * ASTR;
#pragma unroll
    for (int i = 0; i < Tt; i++)
        hs[i * HID + tid] = __bfloat162float(hhi[base + i * HID + tid]) +
                            __bfloat162float(hlo[base + i * HID + tid]);
    aw[tid] = att_w[tid];
    __syncthreads();
    float ab = att_b[0];
    for (int t = 0; t < Tt; t++) {
        red[tid] = hs[t * HID + tid] * aw[tid];
        __syncthreads();
        for (int s = HID / 2; s > 0; s >>= 1) {
            if (tid < s) red[tid] += red[tid + s];
            __syncthreads();
        }
        if (tid == 0) sc[t] = red[0] + ab;
        __syncthreads();
    }
    float mx = -1e30f;
#pragma unroll
    for (int t = 0; t < Tt; t++) mx = fmaxf(mx, sc[t]);
    float a[Tt], sum = 0.f;
#pragma unroll
    for (int t = 0; t < Tt; t++) { a[t] = expf(sc[t] - mx); sum += a[t]; }
    float p = 0.f;
#pragma unroll
    for (int t = 0; t < Tt; t++) p += a[t] * hs[t * HID + tid];
    p /= sum;
    __nv_bfloat16 h = __float2bfloat16(p);
    phi[(size_t)n * HID + tid] = h;
    plo[(size_t)n * HID + tid] = __float2bfloat16(p - __bfloat162float(h));
}

// ---------------- host wrappers ----------------
static inline void gemm_f32(const __nv_bfloat16* Ahi, const __nv_bfloat16* Alo,
                            const __nv_bfloat16* Bhi, const __nv_bfloat16* Blo,
                            float* C, const float* bias, int M, int lda, int Nc, int relu)
{
    dim3 grid(Nc / 128, (M + 255) / 256);
    gemm256<<<grid, 256, G2_SMEM>>>(Ahi, Alo, Bhi, Blo, C, nullptr, nullptr,
                                    bias, M, lda, Nc, relu, 0);
}
static inline void gemm_sp(const __nv_bfloat16* Ahi, const __nv_bfloat16* Alo,
                           const __nv_bfloat16* Bhi, const __nv_bfloat16* Blo,
                           __nv_bfloat16* Chi, __nv_bfloat16* Clo,
                           const float* bias, int M, int lda, int Nc, int relu)
{
    dim3 grid(Nc / 128, (M + 255) / 256);
    gemm256<<<grid, 256, G2_SMEM>>>(Ahi, Alo, Bhi, Blo, nullptr, Chi, Clo,
                                    bias, M, lda, Nc, relu, 1);
}

extern "C" void kernel_launch(void* const* d_in, const int* in_sizes, int n_in,
                              void* d_out, int out_size)
{
    const float* nodes = (const float*)d_in[0];
    const int*   erow  = (const int*)  d_in[1];
    const int*   ecol  = (const int*)  d_in[2];
    const float* ew    = (const float*)d_in[3];
    const float* raw   = (const float*)d_in[4];
    const float* W1    = (const float*)d_in[5];
    const float* b1    = (const float*)d_in[6];
    const float* W2    = (const float*)d_in[7];
    const float* b2    = (const float*)d_in[8];
    const float* Wih0  = (const float*)d_in[9];
    const float* Whh0  = (const float*)d_in[10];
    const float* bih0  = (const float*)d_in[11];
    const float* bhh0  = (const float*)d_in[12];
    const float* Wih1  = (const float*)d_in[13];
    const float* Whh1  = (const float*)d_in[14];
    const float* bih1  = (const float*)d_in[15];
    const float* bhh1  = (const float*)d_in[16];
    const float* att_w = (const float*)d_in[17];
    const float* att_b = (const float*)d_in[18];
    const float* fcn_w = (const float*)d_in[19];
    const float* fcn_b = (const float*)d_in[20];
    const float* out_w = (const float*)d_in[21];
    const float* out_b = (const float*)d_in[22];
    float* out = (float*)d_out;

    static bool attr_done = false;
    if (!attr_done) {
        cudaFuncSetAttribute(gemm256, cudaFuncAttributeMaxDynamicSharedMemorySize, G2_SMEM);
        cudaFuncSetAttribute(lstm_step_kernel, cudaFuncAttributeMaxDynamicSharedMemorySize, SHBYTES);
        attr_done = true;
    }

    float *bufX, *seq, *xg, *cst, *z;
    __nv_bfloat16 *ahi, *alo, *bhi, *blo, *phi, *plo, *whi, *wlo;
    cudaGetSymbolAddress((void**)&bufX, g_bufX);
    cudaGetSymbolAddress((void**)&seq,  g_seq);
    cudaGetSymbolAddress((void**)&xg,   g_xg);
    cudaGetSymbolAddress((void**)&cst,  g_c);
    cudaGetSymbolAddress((void**)&z,    g_z);
    cudaGetSymbolAddress((void**)&ahi,  g_ahi);
    cudaGetSymbolAddress((void**)&alo,  g_alo);
    cudaGetSymbolAddress((void**)&bhi,  g_bhi);
    cudaGetSymbolAddress((void**)&blo,  g_blo);
    cudaGetSymbolAddress((void**)&phi,  g_phi);
    cudaGetSymbolAddress((void**)&plo,  g_plo);
    cudaGetSymbolAddress((void**)&whi,  g_whi);
    cudaGetSymbolAddress((void**)&wlo,  g_wlo);

    const int M = (int)NT;
    const long long sc_blocks = ((long long)Tt * Ee * 32 + 255) / 256;
    const dim3 lstm_grid(HID / 32, (Nn + 127) / 128);
    const int init_blocks = (int)(((size_t)Nn * HID + 255) / 256);

    // L1: all weight splits (one launch)
    split_weights_all<<<1024, 256>>>(W1, W2, Wih0, Whh0, Wih1, Whh1, fcn_w, whi, wlo);

    // L2: zero agg
    zero_f4<<<4096, 256>>>((float4*)bufX, NT * (size_t)FIN / 4);

    // L3: agg = spmm(nodes)
    spmm_scatter128<<<(unsigned)sc_blocks, 256>>>(nodes, erow, ecol, ew, bufX, FIN, 0);

    // L4: split agg
    split_rows<<<8192, 256>>>(bufX, ahi, alo, (long long)NT, FIN, FIN, 0);

    // L5: x = relu(agg @ W1 + b1) -> split
    gemm_sp(ahi, alo, whi + OFF_W1T, wlo + OFF_W1T, bhi, blo, b1, M, FIN, H1C, 1);

    // L6: support2 = x @ W2  <-- ncu capture target (-s 5 -c 1)
    gemm_f32(bhi, blo, whi + OFF_W2T, wlo + OFF_W2T, bufX, nullptr, M, H1C, H2C, 0);

    // seq = [spmm(support2)+b2 | raw]
    init_seq<<<8192, 256>>>(seq, b2, raw, NT * (size_t)DSEQ);
    spmm_scatter128<<<(unsigned)sc_blocks, 256>>>(bufX, erow, ecol, ew, seq, DSEQ, 1);

    // xg0 = seq @ Wih0^T + bih0
    split_rows<<<8192, 256>>>(seq, bhi, blo, (long long)NT, DSEQ, DSEQP, 0);
    gemm_f32(bhi, blo, whi + OFF_WIH0, wlo + OFF_WIH0, xg, bih0, M, DSEQP, G4, 0);

    // LSTM layer 0 -> split chain in ahi/alo
    lstm_init_kernel<<<init_blocks, 256>>>(xg, bhh0, cst, ahi, alo);
    for (int t = 1; t < Tt; t++) {
        lstm_step_kernel<<<lstm_grid, 256, SHBYTES>>>(
            ahi + (size_t)(t - 1) * HID, alo + (size_t)(t - 1) * HID,
            whi + OFF_WHH0, wlo + OFF_WHH0, xg, bhh0, cst,
            ahi + (size_t)t * HID, alo + (size_t)t * HID, Nn, t);
    }

    // xg1 = hseq0 @ Wih1^T + bih1
    gemm_f32(ahi, alo, whi + OFF_WIH1, wlo + OFF_WIH1, xg, bih1, M, HID, G4, 0);

    // LSTM layer 1 -> split chain (reused)
    lstm_init_kernel<<<init_blocks, 256>>>(xg, bhh1, cst, ahi, alo);
    for (int t = 1; t < Tt; t++) {
        lstm_step_kernel<<<lstm_grid, 256, SHBYTES>>>(
            ahi + (size_t)(t - 1) * HID, alo + (size_t)(t - 1) * HID,
            whi + OFF_WHH1, wlo + OFF_WHH1, xg, bhh1, cst,
            ahi + (size_t)t * HID, alo + (size_t)t * HID, Nn, t);
    }

    // attention pooling (reads split chain) -> split pooled
    attention_pool<<<Nn, HID>>>(ahi, alo, att_w, att_b, phi, plo);

    // z = relu(pooled @ fcn_w + fcn_b)
    gemm_f32(phi, plo, whi + OFF_FCNT, wlo + OFF_FCNT, z, fcn_b, Nn, HID, 128, 1);

    // out = z @ out_w + out_b
    {
        dim3 grid((OUTC + 63) / 64, (Nn + 63) / 64);
        sgemm_kernel<64, 64, 16, 4, 4><<<grid, 256>>>(z, out_w, out, out_b, Nn, 128, OUTC);
    }
}

// round 14
// speedup vs baseline: 1.0496x; 1.0496x over previous
#include <cuda_runtime.h>
#include <cuda_bf16.h>
#include <math.h>
#include <stdint.h>

// ---------------- problem constants ----------------
constexpr int Tt   = 12;
constexpr int Nn   = 30000;
constexpr int Ee   = 480000;
constexpr int FIN  = 128;
constexpr int H1C  = 256;
constexpr int H2C  = 128;
constexpr int RAWC = 20;
constexpr int HID  = 256;
constexpr int OUTC = 64;
constexpr int DSEQ = H2C + RAWC;   // 148
constexpr int DSEQP= 160;          // padded (multiple of 32)
constexpr int G4   = 4 * HID;      // 1024
constexpr int ASTR = Tt * HID;     // 3072
constexpr size_t NT = (size_t)Nn * Tt;  // 360000

// weight split buffer offsets (elements)
constexpr size_t OFF_W1T  = 0;         // [256,128]
constexpr size_t OFF_W2T  = 32768;     // [128,256]
constexpr size_t OFF_WIH0 = 65536;     // [1024,160]
constexpr size_t OFF_WHH0 = 229376;    // [1024,256]
constexpr size_t OFF_WIH1 = 491520;    // [1024,256]
constexpr size_t OFF_WHH1 = 753664;    // [1024,256]
constexpr size_t OFF_FCNT = 1015808;   // [128,256]
constexpr size_t WSPLIT_SZ= 1048576;

// ---------------- scratch ----------------
__device__ float g_bufX[NT * 256];        // agg nodes -> support2
__device__ float g_seq [NT * DSEQ];
__device__ float g_xg  [NT * (size_t)G4];
__device__ float g_c   [(size_t)Nn * HID];
__device__ float g_z   [(size_t)Nn * 128];
__device__ __nv_bfloat16 g_ahi[NT * 256]; // agg split -> hseq0 chain -> hseq1 chain
__device__ __nv_bfloat16 g_alo[NT * 256];
__device__ __nv_bfloat16 g_bhi[NT * 256]; // x split -> seq split
__device__ __nv_bfloat16 g_blo[NT * 256];
__device__ __nv_bfloat16 g_phi[(size_t)Nn * HID];
__device__ __nv_bfloat16 g_plo[(size_t)Nn * HID];
__device__ __nv_bfloat16 g_whi[WSPLIT_SZ];
__device__ __nv_bfloat16 g_wlo[WSPLIT_SZ];

// ---------------- helpers ----------------
__device__ __forceinline__ uint32_t sptr(const void* p) {
    return (uint32_t)__cvta_generic_to_shared(p);
}
__device__ __forceinline__ void ldsm4(uint32_t* r, uint32_t a) {
    asm volatile("ldmatrix.sync.aligned.m8n8.x4.shared.b16 {%0,%1,%2,%3}, [%4];"
                 : "=r"(r[0]), "=r"(r[1]), "=r"(r[2]), "=r"(r[3]) : "r"(a));
}
__device__ __forceinline__ void ldsm2(uint32_t* r, uint32_t a) {
    asm volatile("ldmatrix.sync.aligned.m8n8.x2.shared.b16 {%0,%1}, [%2];"
                 : "=r"(r[0]), "=r"(r[1]) : "r"(a));
}
__device__ __forceinline__ void mma_bf16(float* c, const uint32_t* a, const uint32_t* b) {
    asm volatile("mma.sync.aligned.m16n8k16.row.col.f32.bf16.bf16.f32 "
                 "{%0,%1,%2,%3}, {%4,%5,%6,%7}, {%8,%9}, {%0,%1,%2,%3};"
                 : "+f"(c[0]), "+f"(c[1]), "+f"(c[2]), "+f"(c[3])
                 : "r"(a[0]), "r"(a[1]), "r"(a[2]), "r"(a[3]), "r"(b[0]), "r"(b[1]));
}
__device__ __forceinline__ void cpasync16(void* dst, const void* src, bool pred) {
    int sz = pred ? 16 : 0;
    asm volatile("cp.async.cg.shared.global [%0], [%1], 16, %2;"
                 :: "r"(sptr(dst)), "l"(src), "r"(sz));
}
__device__ __forceinline__ void red4(float* addr, float x, float y, float z, float w) {
    asm volatile("red.global.add.v4.f32 [%0], {%1,%2,%3,%4};"
                 :: "l"(addr), "f"(x), "f"(y), "f"(z), "f"(w) : "memory");
}
__device__ __forceinline__ float sigmoidf_(float x) { return 1.f / (1.f + expf(-x)); }

#define PITCH 40
#define BUFE  (128 * PITCH)
#define SHBYTES (2 * 4 * BUFE * 2)   // 81920

// =====================================================================
// R6-proven GEMM: 128x128 block, 8 warps (2m x 4n), warp 64x32,
// 3-pass bf16 split, 2-stage cp.async, 2 blocks/SM.
// A:[M,lda] split row-major; B:[Nc,lda] split (B^T). Nc % 128 == 0.
// =====================================================================
__global__ void __launch_bounds__(256, 2) mma_gemm_bf16(
    const __nv_bfloat16* __restrict__ Ahi, const __nv_bfloat16* __restrict__ Alo,
    const __nv_bfloat16* __restrict__ Bhi, const __nv_bfloat16* __restrict__ Blo,
    float* __restrict__ C, __nv_bfloat16* __restrict__ Chi, __nv_bfloat16* __restrict__ Clo,
    const float* __restrict__ bias,
    int M, int lda, int Nc, int relu_c, int out_split)
{
    extern __shared__ __nv_bfloat16 smem[];

    const int tid  = threadIdx.x;
    const int lane = tid & 31;
    const int warp = tid >> 5;
    const int warp_m = (warp >> 2) << 6;  // 0 or 64
    const int warp_n = (warp & 3) << 5;   // 0,32,64,96
    const int brow = blockIdx.y * 128;
    const int bcol = blockIdx.x * 128;

    float acc[4][4][4];
#pragma unroll
    for (int i = 0; i < 4; i++)
#pragma unroll
        for (int j = 0; j < 4; j++)
#pragma unroll
            for (int v = 0; v < 4; v++) acc[i][j][v] = 0.f;

    const int l_row = tid >> 1;
    const int l_kc  = (tid & 1) << 4;
    const int gr  = brow + l_row;
    const bool okA = (gr < M);
    const int grc = okA ? gr : 0;
    const int gn  = bcol + l_row;

    const int a_lrow = (lane & 7) + ((lane >> 3) & 1) * 8;
    const int a_lcol = (lane >> 4) * 8;
    const int b_lrow = lane & 7;
    const int b_lcol = ((lane >> 3) & 1) * 8;

    auto load_stage = [&](int s, int k0) {
        __nv_bfloat16* base = smem + s * 4 * BUFE;
        size_t aoff = (size_t)grc * lda + k0 + l_kc;
        size_t boff = (size_t)gn  * lda + k0 + l_kc;
        int so = l_row * PITCH + l_kc;
        cpasync16(base + 0 * BUFE + so,     Ahi + aoff,     okA);
        cpasync16(base + 0 * BUFE + so + 8, Ahi + aoff + 8, okA);
        cpasync16(base + 1 * BUFE + so,     Alo + aoff,     okA);
        cpasync16(base + 1 * BUFE + so + 8, Alo + aoff + 8, okA);
        cpasync16(base + 2 * BUFE + so,     Bhi + boff,     true);
        cpasync16(base + 2 * BUFE + so + 8, Bhi + boff + 8, true);
        cpasync16(base + 3 * BUFE + so,     Blo + boff,     true);
        cpasync16(base + 3 * BUFE + so + 8, Blo + boff + 8, true);
    };

    auto compute = [&](int s) {
        __nv_bfloat16* As_hi = smem + (s * 4 + 0) * BUFE;
        __nv_bfloat16* As_lo = smem + (s * 4 + 1) * BUFE;
        __nv_bfloat16* Bs_hi = smem + (s * 4 + 2) * BUFE;
        __nv_bfloat16* Bs_lo = smem + (s * 4 + 3) * BUFE;
#pragma unroll
        for (int st = 0; st < 2; st++) {
            int kb = st * 16;
            uint32_t A[4][4], Bh[4][2], Bl[4][2];
            // pass 1: Ah x Bh
#pragma unroll
            for (int mi = 0; mi < 4; mi++)
                ldsm4(A[mi], sptr(&As_hi[(warp_m + mi * 16 + a_lrow) * PITCH + kb + a_lcol]));
#pragma unroll
            for (int ni = 0; ni < 4; ni++)
                ldsm2(Bh[ni], sptr(&Bs_hi[(warp_n + ni * 8 + b_lrow) * PITCH + kb + b_lcol]));
#pragma unroll
            for (int mi = 0; mi < 4; mi++)
#pragma unroll
                for (int ni = 0; ni < 4; ni++) mma_bf16(acc[mi][ni], A[mi], Bh[ni]);
            // pass 2: Ah x Bl
#pragma unroll
            for (int ni = 0; ni < 4; ni++)
                ldsm2(Bl[ni], sptr(&Bs_lo[(warp_n + ni * 8 + b_lrow) * PITCH + kb + b_lcol]));
#pragma unroll
            for (int mi = 0; mi < 4; mi++)
#pragma unroll
                for (int ni = 0; ni < 4; ni++) mma_bf16(acc[mi][ni], A[mi], Bl[ni]);
            // pass 3: Al x Bh
#pragma unroll
            for (int mi = 0; mi < 4; mi++)
                ldsm4(A[mi], sptr(&As_lo[(warp_m + mi * 16 + a_lrow) * PITCH + kb + a_lcol]));
#pragma unroll
            for (int mi = 0; mi < 4; mi++)
#pragma unroll
                for (int ni = 0; ni < 4; ni++) mma_bf16(acc[mi][ni], A[mi], Bh[ni]);
        }
    };

    const int KT = lda >> 5;
    load_stage(0, 0);
    asm volatile("cp.async.commit_group;" ::: "memory");
    for (int kt = 0; kt < KT; kt++) {
        if (kt + 1 < KT) {
            load_stage((kt + 1) & 1, (kt + 1) << 5);
            asm volatile("cp.async.commit_group;" ::: "memory");
            asm volatile("cp.async.wait_group 1;" ::: "memory");
        } else {
            asm volatile("cp.async.wait_group 0;" ::: "memory");
        }
        __syncthreads();
        compute(kt & 1);
        __syncthreads();
    }

    // epilogue
#pragma unroll
    for (int mi = 0; mi < 4; mi++) {
#pragma unroll
        for (int ni = 0; ni < 4; ni++) {
            int n0 = bcol + warp_n + ni * 8 + (lane & 3) * 2;
            float bx = bias ? bias[n0] : 0.f;
            float by = bias ? bias[n0 + 1] : 0.f;
            int m0 = brow + warp_m + mi * 16 + (lane >> 2);
#pragma unroll
            for (int h = 0; h < 2; h++) {
                int m = m0 + h * 8;
                if (m >= M) continue;
                float vx = acc[mi][ni][h * 2 + 0] + bx;
                float vy = acc[mi][ni][h * 2 + 1] + by;
                if (relu_c) { vx = fmaxf(vx, 0.f); vy = fmaxf(vy, 0.f); }
                if (out_split) {
                    __nv_bfloat16 h0 = __float2bfloat16(vx);
                    __nv_bfloat16 h1 = __float2bfloat16(vy);
                    __nv_bfloat162 hv; hv.x = h0; hv.y = h1;
                    __nv_bfloat162 lv;
                    lv.x = __float2bfloat16(vx - __bfloat162float(h0));
                    lv.y = __float2bfloat16(vy - __bfloat162float(h1));
                    *reinterpret_cast<__nv_bfloat162*>(&Chi[(size_t)m * Nc + n0]) = hv;
                    *reinterpret_cast<__nv_bfloat162*>(&Clo[(size_t)m * Nc + n0]) = lv;
                } else {
                    float2 v; v.x = vx; v.y = vy;
                    *reinterpret_cast<float2*>(&C[(size_t)m * Nc + n0]) = v;
                }
            }
        }
    }
}

// =====================================================================
// Fused LSTM step (R6, proven): gates = h_{t-1}@Whh^T (+xg_t+bhh), pointwise.
// =====================================================================
__global__ void __launch_bounds__(256, 2) lstm_step_kernel(
    const __nv_bfloat16* __restrict__ Ahi, const __nv_bfloat16* __restrict__ Alo,
    const __nv_bfloat16* __restrict__ Bhi, const __nv_bfloat16* __restrict__ Blo,
    const float* __restrict__ xg, const float* __restrict__ bhh,
    float* __restrict__ cst,
    __nv_bfloat16* __restrict__ Ohi, __nv_bfloat16* __restrict__ Olo,
    int M, int t)
{
    extern __shared__ __nv_bfloat16 smem2[];

    const int tid  = threadIdx.x;
    const int lane = tid & 31;
    const int warp = tid >> 5;
    const int warp_m = (warp >> 2) << 6;
    const int warp_n = (warp & 3) << 5;
    const int brow = blockIdx.y * 128;
    const int hc0  = blockIdx.x * 32;

    float acc[4][4][4];
#pragma unroll
    for (int i = 0; i < 4; i++)
#pragma unroll
        for (int j = 0; j < 4; j++)
#pragma unroll
            for (int v = 0; v < 4; v++) acc[i][j][v] = 0.f;

    const int l_row = tid >> 1;
    const int l_kc  = (tid & 1) << 4;
    const int gr  = brow + l_row;
    const bool okA = (gr < M);
    const int grc = okA ? gr : 0;
    const int b_gate = l_row >> 5;
    const int b_idx  = l_row & 31;
    const int gBrow  = b_gate * 256 + hc0 + b_idx;

    const int a_lrow = (lane & 7) + ((lane >> 3) & 1) * 8;
    const int a_lcol = (lane >> 4) * 8;
    const int b_lrow = lane & 7;
    const int b_lcol = ((lane >> 3) & 1) * 8;

    auto load_stage = [&](int s, int k0) {
        __nv_bfloat16* base = smem2 + s * 4 * BUFE;
        size_t aoff = (size_t)grc * ASTR + k0 + l_kc;
        size_t boff = (size_t)gBrow * HID + k0 + l_kc;
        int so = l_row * PITCH + l_kc;
        cpasync16(base + 0 * BUFE + so,     Ahi + aoff,     okA);
        cpasync16(base + 0 * BUFE + so + 8, Ahi + aoff + 8, okA);
        cpasync16(base + 1 * BUFE + so,     Alo + aoff,     okA);
        cpasync16(base + 1 * BUFE + so + 8, Alo + aoff + 8, okA);
        cpasync16(base + 2 * BUFE + so,     Bhi + boff,     true);
        cpasync16(base + 2 * BUFE + so + 8, Bhi + boff + 8, true);
        cpasync16(base + 3 * BUFE + so,     Blo + boff,     true);
        cpasync16(base + 3 * BUFE + so + 8, Blo + boff + 8, true);
    };

    auto compute = [&](int s) {
        __nv_bfloat16* As_hi = smem2 + (s * 4 + 0) * BUFE;
        __nv_bfloat16* As_lo = smem2 + (s * 4 + 1) * BUFE;
        __nv_bfloat16* Bs_hi = smem2 + (s * 4 + 2) * BUFE;
        __nv_bfloat16* Bs_lo = smem2 + (s * 4 + 3) * BUFE;
#pragma unroll
        for (int st = 0; st < 2; st++) {
            int kb = st * 16;
            uint32_t A[4][4], Bh[4][2], Bl[4][2];
#pragma unroll
            for (int mi = 0; mi < 4; mi++)
                ldsm4(A[mi], sptr(&As_hi[(warp_m + mi * 16 + a_lrow) * PITCH + kb + a_lcol]));
#pragma unroll
            for (int ni = 0; ni < 4; ni++)
                ldsm2(Bh[ni], sptr(&Bs_hi[(warp_n + ni * 8 + b_lrow) * PITCH + kb + b_lcol]));
#pragma unroll
            for (int mi = 0; mi < 4; mi++)
#pragma unroll
                for (int ni = 0; ni < 4; ni++) mma_bf16(acc[mi][ni], A[mi], Bh[ni]);
#pragma unroll
            for (int ni = 0; ni < 4; ni++)
                ldsm2(Bl[ni], sptr(&Bs_lo[(warp_n + ni * 8 + b_lrow) * PITCH + kb + b_lcol]));
#pragma unroll
            for (int mi = 0; mi < 4; mi++)
#pragma unroll
                for (int ni = 0; ni < 4; ni++) mma_bf16(acc[mi][ni], A[mi], Bl[ni]);
#pragma unroll
            for (int mi = 0; mi < 4; mi++)
                ldsm4(A[mi], sptr(&As_lo[(warp_m + mi * 16 + a_lrow) * PITCH + kb + a_lcol]));
#pragma unroll
            for (int mi = 0; mi < 4; mi++)
#pragma unroll
                for (int ni = 0; ni < 4; ni++) mma_bf16(acc[mi][ni], A[mi], Bh[ni]);
        }
    };

    const int KT = HID >> 5;
    load_stage(0, 0);
    asm volatile("cp.async.commit_group;" ::: "memory");
    for (int kt = 0; kt < KT; kt++) {
        if (kt + 1 < KT) {
            load_stage((kt + 1) & 1, (kt + 1) << 5);
            asm volatile("cp.async.commit_group;" ::: "memory");
            asm volatile("cp.async.wait_group 1;" ::: "memory");
        } else {
            asm volatile("cp.async.wait_group 0;" ::: "memory");
        }
        __syncthreads();
        compute(kt & 1);
        __syncthreads();
    }

    float* gsm = reinterpret_cast<float*>(smem2);
#pragma unroll
    for (int mi = 0; mi < 4; mi++) {
#pragma unroll
        for (int ni = 0; ni < 4; ni++) {
            int lc = warp_n + ni * 8 + (lane & 3) * 2;
            int r0 = warp_m + mi * 16 + (lane >> 2);
#pragma unroll
            for (int h = 0; h < 2; h++) {
                int r = r0 + h * 8;
                gsm[r * 132 + lc]     = acc[mi][ni][h * 2 + 0];
                gsm[r * 132 + lc + 1] = acc[mi][ni][h * 2 + 1];
            }
        }
    }
    __syncthreads();

    for (int idx = tid; idx < 128 * 32; idx += 256) {
        int row = idx >> 5;
        int col = idx & 31;
        int m = brow + row;
        if (m >= M) continue;
        int hc = hc0 + col;
        size_t xr = ((size_t)m * Tt + t) * G4;
        float gi = gsm[row * 132 +  0 + col] + xg[xr + hc]       + bhh[hc];
        float gf = gsm[row * 132 + 32 + col] + xg[xr + 256 + hc] + bhh[256 + hc];
        float gg = gsm[row * 132 + 64 + col] + xg[xr + 512 + hc] + bhh[512 + hc];
        float go = gsm[row * 132 + 96 + col] + xg[xr + 768 + hc] + bhh[768 + hc];
        size_t ci = (size_t)m * HID + hc;
        float cn = sigmoidf_(gf) * cst[ci] + sigmoidf_(gi) * tanhf(gg);
        float hn = sigmoidf_(go) * tanhf(cn);
        cst[ci] = cn;
        size_t ho = (size_t)m * ASTR + hc;
        __nv_bfloat16 hh = __float2bfloat16(hn);
        Ohi[ho] = hh;
        Olo[ho] = __float2bfloat16(hn - __bfloat162float(hh));
    }
}

__global__ void lstm_init_kernel(const float* __restrict__ xg, const float* __restrict__ bhh,
                                 float* __restrict__ cst,
                                 __nv_bfloat16* __restrict__ Ohi, __nv_bfloat16* __restrict__ Olo)
{
    size_t idx = (size_t)blockIdx.x * blockDim.x + threadIdx.x;
    if (idx >= (size_t)Nn * HID) return;
    size_t n = idx >> 8;
    int hc = (int)(idx & 255);
    size_t xr = n * Tt * (size_t)G4;
    float gi = xg[xr + hc]       + bhh[hc];
    float gg = xg[xr + 512 + hc] + bhh[512 + hc];
    float go = xg[xr + 768 + hc] + bhh[768 + hc];
    float cn = sigmoidf_(gi) * tanhf(gg);
    float hn = sigmoidf_(go) * tanhf(cn);
    cst[idx] = cn;
    size_t ho = n * ASTR + hc;
    __nv_bfloat16 hh = __float2bfloat16(hn);
    Ohi[ho] = hh;
    Olo[ho] = __float2bfloat16(hn - __bfloat162float(hh));
}

// ---------------- split / init kernels ----------------
__global__ void split_rows(const float* __restrict__ src,
                           __nv_bfloat16* __restrict__ hi, __nv_bfloat16* __restrict__ lo,
                           long long R, int C, int Cp, int relu)
{
    long long total = R * (Cp >> 2);
    long long stride = (long long)gridDim.x * blockDim.x;
    int gpr = Cp >> 2;
    for (long long g = (long long)blockIdx.x * blockDim.x + threadIdx.x; g < total; g += stride) {
        int gp = (int)(g % gpr);
        long long r = g / gpr;
        int c = gp << 2;
        float4 v = make_float4(0.f, 0.f, 0.f, 0.f);
        if (c + 3 < C) v = *reinterpret_cast<const float4*>(&src[r * C + c]);
        else if (c < C) {
            float tmp[4] = {0.f, 0.f, 0.f, 0.f};
            for (int e = 0; e < 4 && c + e < C; e++) tmp[e] = src[r * C + c + e];
            v.x = tmp[0]; v.y = tmp[1]; v.z = tmp[2]; v.w = tmp[3];
        }
        if (relu) {
            v.x = fmaxf(v.x, 0.f); v.y = fmaxf(v.y, 0.f);
            v.z = fmaxf(v.z, 0.f); v.w = fmaxf(v.w, 0.f);
        }
        float vv[4] = {v.x, v.y, v.z, v.w};
        __nv_bfloat16 h4[4], l4[4];
#pragma unroll
        for (int e = 0; e < 4; e++) {
            h4[e] = __float2bfloat16(vv[e]);
            l4[e] = __float2bfloat16(vv[e] - __bfloat162float(h4[e]));
        }
        *reinterpret_cast<uint2*>(&hi[r * Cp + c]) = *reinterpret_cast<uint2*>(h4);
        *reinterpret_cast<uint2*>(&lo[r * Cp + c]) = *reinterpret_cast<uint2*>(l4);
    }
}

__global__ void split_weights_all(const float* __restrict__ W1, const float* __restrict__ W2,
                                  const float* __restrict__ Wih0, const float* __restrict__ Whh0,
                                  const float* __restrict__ Wih1, const float* __restrict__ Whh1,
                                  const float* __restrict__ fcn_w,
                                  __nv_bfloat16* __restrict__ whi, __nv_bfloat16* __restrict__ wlo)
{
    int stride = gridDim.x * blockDim.x;
    for (int i = blockIdx.x * blockDim.x + threadIdx.x; i < (int)WSPLIT_SZ; i += stride) {
        float v;
        if (i < 32768) {                       // W1T [256,128] <- W1[128,256]
            int n = i >> 7, k = i & 127; v = W1[k * 256 + n];
        } else if (i < 65536) {                // W2T [128,256] <- W2[256,128]
            int j = i - 32768; int n = j >> 8, k = j & 255; v = W2[k * 128 + n];
        } else if (i < 229376) {               // WIH0 [1024,160] pad from [1024,148]
            int j = i - 65536; int r = j / DSEQP, c = j % DSEQP;
            v = (c < DSEQ) ? Wih0[r * DSEQ + c] : 0.f;
        } else if (i < 491520) {               // WHH0 [1024,256]
            v = Whh0[i - 229376];
        } else if (i < 753664) {               // WIH1 [1024,256]
            v = Wih1[i - 491520];
        } else if (i < 1015808) {              // WHH1 [1024,256]
            v = Whh1[i - 753664];
        } else {                               // FCNT [128,256] <- fcn_w[256,128]
            int j = i - 1015808; int n = j >> 8, k = j & 255; v = fcn_w[k * 128 + n];
        }
        __nv_bfloat16 h = __float2bfloat16(v);
        whi[i] = h;
        wlo[i] = __float2bfloat16(v - __bfloat162float(h));
    }
}

__global__ void zero_f4(float4* __restrict__ p, size_t n4)
{
    size_t stride = (size_t)gridDim.x * blockDim.x;
    for (size_t i = (size_t)blockIdx.x * blockDim.x + threadIdx.x; i < n4; i += stride)
        p[i] = make_float4(0.f, 0.f, 0.f, 0.f);
}

__global__ void init_seq(float* __restrict__ seq, const float* __restrict__ b2,
                         const float* __restrict__ raw, size_t total)
{
    size_t stride = (size_t)gridDim.x * blockDim.x;
    for (size_t i = (size_t)blockIdx.x * blockDim.x + threadIdx.x; i < total; i += stride) {
        int c = (int)(i % DSEQ);
        size_t nt = i / DSEQ;
        int t = (int)(nt % Tt);
        size_t n = nt / Tt;
        seq[i] = (c < H2C) ? b2[c]
                           : raw[(size_t)t * Nn * RAWC + n * RAWC + (c - H2C)];
    }
}

// ---------------- fp32 fallback GEMM (final out gemm, Nc=64) ----------------
template<int BM, int BN, int BK, int TM, int TN>
__global__ void sgemm_kernel(const float* __restrict__ A, const float* __restrict__ B,
                             float* __restrict__ C, const float* __restrict__ bias,
                             int M, int K, int Nc)
{
    __shared__ float As[BK][BM];
    __shared__ float Bs[BK][BN];
    const int tid = threadIdx.x;
    const int brow = blockIdx.y * BM;
    const int bcol = blockIdx.x * BN;
    const int trow = (tid / (BN / TN)) * TM;
    const int tcol = (tid % (BN / TN)) * TN;

    float acc[TM][TN];
#pragma unroll
    for (int i = 0; i < TM; i++)
#pragma unroll
        for (int j = 0; j < TN; j++) acc[i][j] = 0.f;

    for (int k0 = 0; k0 < K; k0 += BK) {
#pragma unroll
        for (int i = 0; i < (BM * BK) / 256; i++) {
            int l = tid + i * 256;
            int m = l / BK, k = l % BK;
            int gr = brow + m, gk = k0 + k;
            As[k][m] = (gr < M && gk < K) ? A[(size_t)gr * K + gk] : 0.f;
        }
#pragma unroll
        for (int i = 0; i < (BK * BN) / 256; i++) {
            int l = tid + i * 256;
            int k = l / BN, n = l % BN;
            int gk = k0 + k, gn = bcol + n;
            Bs[k][n] = (gk < K && gn < Nc) ? B[(size_t)gk * Nc + gn] : 0.f;
        }
        __syncthreads();
#pragma unroll
        for (int k = 0; k < BK; k++) {
            float ar[TM], br[TN];
#pragma unroll
            for (int i = 0; i < TM; i++) ar[i] = As[k][trow + i];
#pragma unroll
            for (int j = 0; j < TN; j++) br[j] = Bs[k][tcol + j];
#pragma unroll
            for (int i = 0; i < TM; i++)
#pragma unroll
                for (int j = 0; j < TN; j++) acc[i][j] = fmaf(ar[i], br[j], acc[i][j]);
        }
        __syncthreads();
    }
#pragma unroll
    for (int i = 0; i < TM; i++) {
        int gr = brow + trow + i;
        if (gr >= M) continue;
#pragma unroll
        for (int j = 0; j < TN; j++) {
            int gn = bcol + tcol + j;
            if (gn >= Nc) continue;
            float v = acc[i][j];
            if (bias) v += bias[gn];
            C[(size_t)gr * Nc + gn] = v;
        }
    }
}

// ---------------- SpMM scatter (128-col) ----------------
__global__ void spmm_scatter128(const float* __restrict__ src,
                                const int* __restrict__ erow, const int* __restrict__ ecol,
                                const float* __restrict__ ew,
                                float* __restrict__ dst,
                                int dst_ld, int dst_layout)
{
    long long warp = ((long long)blockIdx.x * blockDim.x + threadIdx.x) >> 5;
    int lane = threadIdx.x & 31;
    if (warp >= (long long)Tt * Ee) return;
    int t = (int)(warp / Ee);
    int e = (int)(warp % Ee);
    size_t eoff = (size_t)t * Ee + e;
    int r = erow[eoff];
    int c = ecol[eoff];
    float w = ew[eoff];
    const float* s = src + ((size_t)t * Nn + c) * 128;
    size_t doff = (dst_layout == 0) ? ((size_t)t * Nn + r) * (size_t)dst_ld
                                    : ((size_t)r * Tt + t) * (size_t)dst_ld;
    float* d = dst + doff;
    int j = lane << 2;
    float4 v = *reinterpret_cast<const float4*>(&s[j]);
    red4(&d[j], w * v.x, w * v.y, w * v.z, w * v.w);
}

// ---------------- attention pooling (reads split hseq chain) ----------------
__global__ void attention_pool(const __nv_bfloat16* __restrict__ hhi,
                               const __nv_bfloat16* __restrict__ hlo,
                               const float* __restrict__ att_w,
                               const float* __restrict__ att_b,
                               __nv_bfloat16* __restrict__ phi,
                               __nv_bfloat16* __restrict__ plo)
{
    __shared__ float hs[Tt * HID];
    __shared__ float aw[HID];
    __shared__ float red[HID];
    __shared__ float sc[Tt];
    int n = blockIdx.x;
    int tid = threadIdx.x;
    size_t base = (size_t)n * ASTR;
#pragma unroll
    for (int i = 0; i < Tt; i++)
        hs[i * HID + tid] = __bfloat162float(hhi[base + i * HID + tid]) +
                            __bfloat162float(hlo[base + i * HID + tid]);
    aw[tid] = att_w[tid];
    __syncthreads();
    float ab = att_b[0];
    for (int t = 0; t < Tt; t++) {
        red[tid] = hs[t * HID + tid] * aw[tid];
        __syncthreads();
        for (int s = HID / 2; s > 0; s >>= 1) {
            if (tid < s) red[tid] += red[tid + s];
            __syncthreads();
        }
        if (tid == 0) sc[t] = red[0] + ab;
        __syncthreads();
    }
    float mx = -1e30f;
#pragma unroll
    for (int t = 0; t < Tt; t++) mx = fmaxf(mx, sc[t]);
    float a[Tt], sum = 0.f;
#pragma unroll
    for (int t = 0; t < Tt; t++) { a[t] = expf(sc[t] - mx); sum += a[t]; }
    float p = 0.f;
#pragma unroll
    for (int t = 0; t < Tt; t++) p += a[t] * hs[t * HID + tid];
    p /= sum;
    __nv_bfloat16 h = __float2bfloat16(p);
    phi[(size_t)n * HID + tid] = h;
    plo[(size_t)n * HID + tid] = __float2bfloat16(p - __bfloat162float(h));
}

// ---------------- host wrappers ----------------
static inline void gemm_f32(const __nv_bfloat16* Ahi, const __nv_bfloat16* Alo,
                            const __nv_bfloat16* Bhi, const __nv_bfloat16* Blo,
                            float* C, const float* bias, int M, int lda, int Nc, int relu)
{
    dim3 grid(Nc / 128, (M + 127) / 128);
    mma_gemm_bf16<<<grid, 256, SHBYTES>>>(Ahi, Alo, Bhi, Blo, C, nullptr, nullptr,
                                          bias, M, lda, Nc, relu, 0);
}
static inline void gemm_sp(const __nv_bfloat16* Ahi, const __nv_bfloat16* Alo,
                           const __nv_bfloat16* Bhi, const __nv_bfloat16* Blo,
                           __nv_bfloat16* Chi, __nv_bfloat16* Clo,
                           const float* bias, int M, int lda, int Nc, int relu)
{
    dim3 grid(Nc / 128, (M + 127) / 128);
    mma_gemm_bf16<<<grid, 256, SHBYTES>>>(Ahi, Alo, Bhi, Blo, nullptr, Chi, Clo,
                                          bias, M, lda, Nc, relu, 1);
}

extern "C" void kernel_launch(void* const* d_in, const int* in_sizes, int n_in,
                              void* d_out, int out_size)
{
    const float* nodes = (const float*)d_in[0];
    const int*   erow  = (const int*)  d_in[1];
    const int*   ecol  = (const int*)  d_in[2];
    const float* ew    = (const float*)d_in[3];
    const float* raw   = (const float*)d_in[4];
    const float* W1    = (const float*)d_in[5];
    const float* b1    = (const float*)d_in[6];
    const float* W2    = (const float*)d_in[7];
    const float* b2    = (const float*)d_in[8];
    const float* Wih0  = (const float*)d_in[9];
    const float* Whh0  = (const float*)d_in[10];
    const float* bih0  = (const float*)d_in[11];
    const float* bhh0  = (const float*)d_in[12];
    const float* Wih1  = (const float*)d_in[13];
    const float* Whh1  = (const float*)d_in[14];
    const float* bih1  = (const float*)d_in[15];
    const float* bhh1  = (const float*)d_in[16];
    const float* att_w = (const float*)d_in[17];
    const float* att_b = (const float*)d_in[18];
    const float* fcn_w = (const float*)d_in[19];
    const float* fcn_b = (const float*)d_in[20];
    const float* out_w = (const float*)d_in[21];
    const float* out_b = (const float*)d_in[22];
    float* out = (float*)d_out;

    static bool attr_done = false;
    if (!attr_done) {
        cudaFuncSetAttribute(mma_gemm_bf16, cudaFuncAttributeMaxDynamicSharedMemorySize, SHBYTES);
        cudaFuncSetAttribute(lstm_step_kernel, cudaFuncAttributeMaxDynamicSharedMemorySize, SHBYTES);
        attr_done = true;
    }

    float *bufX, *seq, *xg, *cst, *z;
    __nv_bfloat16 *ahi, *alo, *bhi, *blo, *phi, *plo, *whi, *wlo;
    cudaGetSymbolAddress((void**)&bufX, g_bufX);
    cudaGetSymbolAddress((void**)&seq,  g_seq);
    cudaGetSymbolAddress((void**)&xg,   g_xg);
    cudaGetSymbolAddress((void**)&cst,  g_c);
    cudaGetSymbolAddress((void**)&z,    g_z);
    cudaGetSymbolAddress((void**)&ahi,  g_ahi);
    cudaGetSymbolAddress((void**)&alo,  g_alo);
    cudaGetSymbolAddress((void**)&bhi,  g_bhi);
    cudaGetSymbolAddress((void**)&blo,  g_blo);
    cudaGetSymbolAddress((void**)&phi,  g_phi);
    cudaGetSymbolAddress((void**)&plo,  g_plo);
    cudaGetSymbolAddress((void**)&whi,  g_whi);
    cudaGetSymbolAddress((void**)&wlo,  g_wlo);

    const int M = (int)NT;
    const long long sc_blocks = ((long long)Tt * Ee * 32 + 255) / 256;
    const dim3 lstm_grid(HID / 32, (Nn + 127) / 128);
    const int init_blocks = (int)(((size_t)Nn * HID + 255) / 256);

    // L1: all weight splits (one launch)
    split_weights_all<<<1024, 256>>>(W1, W2, Wih0, Whh0, Wih1, Whh1, fcn_w, whi, wlo);

    // L2: zero agg
    zero_f4<<<4096, 256>>>((float4*)bufX, NT * (size_t)FIN / 4);

    // L3: agg = spmm(nodes)
    spmm_scatter128<<<(unsigned)sc_blocks, 256>>>(nodes, erow, ecol, ew, bufX, FIN, 0);

    // L4: split agg
    split_rows<<<8192, 256>>>(bufX, ahi, alo, (long long)NT, FIN, FIN, 0);

    // L5: x = relu(agg @ W1 + b1) -> split
    gemm_sp(ahi, alo, whi + OFF_W1T, wlo + OFF_W1T, bhi, blo, b1, M, FIN, H1C, 1);

    // L6: support2 = x @ W2  <-- ncu capture lands here (-s 5 -c 1)
    gemm_f32(bhi, blo, whi + OFF_W2T, wlo + OFF_W2T, bufX, nullptr, M, H1C, H2C, 0);

    // seq = [spmm(support2)+b2 | raw]
    init_seq<<<8192, 256>>>(seq, b2, raw, NT * (size_t)DSEQ);
    spmm_scatter128<<<(unsigned)sc_blocks, 256>>>(bufX, erow, ecol, ew, seq, DSEQ, 1);

    // xg0 = seq @ Wih0^T + bih0
    split_rows<<<8192, 256>>>(seq, bhi, blo, (long long)NT, DSEQ, DSEQP, 0);
    gemm_f32(bhi, blo, whi + OFF_WIH0, wlo + OFF_WIH0, xg, bih0, M, DSEQP, G4, 0);

    // LSTM layer 0 -> split chain in ahi/alo
    lstm_init_kernel<<<init_blocks, 256>>>(xg, bhh0, cst, ahi, alo);
    for (int t = 1; t < Tt; t++) {
        lstm_step_kernel<<<lstm_grid, 256, SHBYTES>>>(
            ahi + (size_t)(t - 1) * HID, alo + (size_t)(t - 1) * HID,
            whi + OFF_WHH0, wlo + OFF_WHH0, xg, bhh0, cst,
            ahi + (size_t)t * HID, alo + (size_t)t * HID, Nn, t);
    }

    // xg1 = hseq0 @ Wih1^T + bih1
    gemm_f32(ahi, alo, whi + OFF_WIH1, wlo + OFF_WIH1, xg, bih1, M, HID, G4, 0);

    // LSTM layer 1 -> split chain (reused)
    lstm_init_kernel<<<init_blocks, 256>>>(xg, bhh1, cst, ahi, alo);
    for (int t = 1; t < Tt; t++) {
        lstm_step_kernel<<<lstm_grid, 256, SHBYTES>>>(
            ahi + (size_t)(t - 1) * HID, alo + (size_t)(t - 1) * HID,
            whi + OFF_WHH1, wlo + OFF_WHH1, xg, bhh1, cst,
            ahi + (size_t)t * HID, alo + (size_t)t * HID, Nn, t);
    }

    // attention pooling (reads split chain) -> split pooled
    attention_pool<<<Nn, HID>>>(ahi, alo, att_w, att_b, phi, plo);

    // z = relu(pooled @ fcn_w + fcn_b)
    gemm_f32(phi, plo, whi + OFF_FCNT, wlo + OFF_FCNT, z, fcn_b, Nn, HID, 128, 1);

    // out = z @ out_w + out_b
    {
        dim3 grid((OUTC + 63) / 64, (Nn + 63) / 64);
        sgemm_kernel<64, 64, 16, 4, 4><<<grid, 256>>>(z, out_w, out, out_b, Nn, 128, OUTC);
    }
}

// round 15
// speedup vs baseline: 1.0577x; 1.0077x over previous
#include <cuda_runtime.h>
#include <cuda_bf16.h>
#include <math.h>
#include <stdint.h>

// ---------------- problem constants ----------------
constexpr int Tt   = 12;
constexpr int Nn   = 30000;
constexpr int Ee   = 480000;
constexpr int FIN  = 128;
constexpr int H1C  = 256;
constexpr int H2C  = 128;
constexpr int RAWC = 20;
constexpr int HID  = 256;
constexpr int OUTC = 64;
constexpr int DSEQ = H2C + RAWC;   // 148
constexpr int DSEQP= 160;          // padded (multiple of 32)
constexpr int G4   = 4 * HID;      // 1024
constexpr int ASTR = Tt * HID;     // 3072
constexpr size_t NT = (size_t)Nn * Tt;  // 360000

// weight split buffer offsets (elements)
constexpr size_t OFF_W1T  = 0;         // [256,128]
constexpr size_t OFF_W2T  = 32768;     // [128,256]
constexpr size_t OFF_WIH0 = 65536;     // [1024,160]
constexpr size_t OFF_WHH0 = 229376;    // [1024,256]
constexpr size_t OFF_WIH1 = 491520;    // [1024,256]
constexpr size_t OFF_WHH1 = 753664;    // [1024,256]
constexpr size_t OFF_FCNT = 1015808;   // [128,256]
constexpr size_t WSPLIT_SZ= 1048576;

// ---------------- scratch ----------------
__device__ float g_bufX[NT * 256];        // agg nodes -> support2
__device__ float g_seq [NT * DSEQ];
__device__ float g_xg  [NT * (size_t)G4];
__device__ float g_c   [(size_t)Nn * HID];
__device__ float g_z   [(size_t)Nn * 128];
__device__ __nv_bfloat16 g_ahi[NT * 256]; // agg split -> hseq0 chain -> hseq1 chain
__device__ __nv_bfloat16 g_alo[NT * 256];
__device__ __nv_bfloat16 g_bhi[NT * 256]; // x split -> seq split
__device__ __nv_bfloat16 g_blo[NT * 256];
__device__ __nv_bfloat16 g_phi[(size_t)Nn * HID];
__device__ __nv_bfloat16 g_plo[(size_t)Nn * HID];
__device__ __nv_bfloat16 g_whi[WSPLIT_SZ];
__device__ __nv_bfloat16 g_wlo[WSPLIT_SZ];

// ---------------- helpers ----------------
__device__ __forceinline__ uint32_t sptr(const void* p) {
    return (uint32_t)__cvta_generic_to_shared(p);
}
__device__ __forceinline__ void ldsm4(uint32_t* r, uint32_t a) {
    asm volatile("ldmatrix.sync.aligned.m8n8.x4.shared.b16 {%0,%1,%2,%3}, [%4];"
                 : "=r"(r[0]), "=r"(r[1]), "=r"(r[2]), "=r"(r[3]) : "r"(a));
}
__device__ __forceinline__ void ldsm2(uint32_t* r, uint32_t a) {
    asm volatile("ldmatrix.sync.aligned.m8n8.x2.shared.b16 {%0,%1}, [%2];"
                 : "=r"(r[0]), "=r"(r[1]) : "r"(a));
}
__device__ __forceinline__ void mma_bf16(float* c, const uint32_t* a, const uint32_t* b) {
    asm volatile("mma.sync.aligned.m16n8k16.row.col.f32.bf16.bf16.f32 "
                 "{%0,%1,%2,%3}, {%4,%5,%6,%7}, {%8,%9}, {%0,%1,%2,%3};"
                 : "+f"(c[0]), "+f"(c[1]), "+f"(c[2]), "+f"(c[3])
                 : "r"(a[0]), "r"(a[1]), "r"(a[2]), "r"(a[3]), "r"(b[0]), "r"(b[1]));
}
__device__ __forceinline__ void cpasync16(void* dst, const void* src, bool pred) {
    int sz = pred ? 16 : 0;
    asm volatile("cp.async.cg.shared.global [%0], [%1], 16, %2;"
                 :: "r"(sptr(dst)), "l"(src), "r"(sz));
}
__device__ __forceinline__ void red4(float* addr, float x, float y, float z, float w) {
    asm volatile("red.global.add.v4.f32 [%0], {%1,%2,%3,%4};"
                 :: "l"(addr), "f"(x), "f"(y), "f"(z), "f"(w) : "memory");
}
__device__ __forceinline__ float sigmoidf_(float x) { return 1.f / (1.f + expf(-x)); }

#define PITCH 40
#define BUFE  (128 * PITCH)
#define SHBYTES (2 * 4 * BUFE * 2)   // 81920

// =====================================================================
// R6-proven GEMM: 128x128 block, 8 warps (2m x 4n), warp 64x32,
// 3-pass bf16 split, 2-stage cp.async, 2 blocks/SM.
// A:[M,lda] split row-major; B:[Nc,lda] split (B^T). Nc % 128 == 0.
// =====================================================================
__global__ void __launch_bounds__(256, 2) mma_gemm_bf16(
    const __nv_bfloat16* __restrict__ Ahi, const __nv_bfloat16* __restrict__ Alo,
    const __nv_bfloat16* __restrict__ Bhi, const __nv_bfloat16* __restrict__ Blo,
    float* __restrict__ C, __nv_bfloat16* __restrict__ Chi, __nv_bfloat16* __restrict__ Clo,
    const float* __restrict__ bias,
    int M, int lda, int Nc, int relu_c, int out_split)
{
    extern __shared__ __nv_bfloat16 smem[];

    const int tid  = threadIdx.x;
    const int lane = tid & 31;
    const int warp = tid >> 5;
    const int warp_m = (warp >> 2) << 6;  // 0 or 64
    const int warp_n = (warp & 3) << 5;   // 0,32,64,96
    const int brow = blockIdx.y * 128;
    const int bcol = blockIdx.x * 128;

    float acc[4][4][4];
#pragma unroll
    for (int i = 0; i < 4; i++)
#pragma unroll
        for (int j = 0; j < 4; j++)
#pragma unroll
            for (int v = 0; v < 4; v++) acc[i][j][v] = 0.f;

    const int l_row = tid >> 1;
    const int l_kc  = (tid & 1) << 4;
    const int gr  = brow + l_row;
    const bool okA = (gr < M);
    const int grc = okA ? gr : 0;
    const int gn  = bcol + l_row;

    const int a_lrow = (lane & 7) + ((lane >> 3) & 1) * 8;
    const int a_lcol = (lane >> 4) * 8;
    const int b_lrow = lane & 7;
    const int b_lcol = ((lane >> 3) & 1) * 8;

    auto load_stage = [&](int s, int k0) {
        __nv_bfloat16* base = smem + s * 4 * BUFE;
        size_t aoff = (size_t)grc * lda + k0 + l_kc;
        size_t boff = (size_t)gn  * lda + k0 + l_kc;
        int so = l_row * PITCH + l_kc;
        cpasync16(base + 0 * BUFE + so,     Ahi + aoff,     okA);
        cpasync16(base + 0 * BUFE + so + 8, Ahi + aoff + 8, okA);
        cpasync16(base + 1 * BUFE + so,     Alo + aoff,     okA);
        cpasync16(base + 1 * BUFE + so + 8, Alo + aoff + 8, okA);
        cpasync16(base + 2 * BUFE + so,     Bhi + boff,     true);
        cpasync16(base + 2 * BUFE + so + 8, Bhi + boff + 8, true);
        cpasync16(base + 3 * BUFE + so,     Blo + boff,     true);
        cpasync16(base + 3 * BUFE + so + 8, Blo + boff + 8, true);
    };

    auto compute = [&](int s) {
        __nv_bfloat16* As_hi = smem + (s * 4 + 0) * BUFE;
        __nv_bfloat16* As_lo = smem + (s * 4 + 1) * BUFE;
        __nv_bfloat16* Bs_hi = smem + (s * 4 + 2) * BUFE;
        __nv_bfloat16* Bs_lo = smem + (s * 4 + 3) * BUFE;
#pragma unroll
        for (int st = 0; st < 2; st++) {
            int kb = st * 16;
            uint32_t A[4][4], Bh[4][2], Bl[4][2];
            // pass 1: Ah x Bh
#pragma unroll
            for (int mi = 0; mi < 4; mi++)
                ldsm4(A[mi], sptr(&As_hi[(warp_m + mi * 16 + a_lrow) * PITCH + kb + a_lcol]));
#pragma unroll
            for (int ni = 0; ni < 4; ni++)
                ldsm2(Bh[ni], sptr(&Bs_hi[(warp_n + ni * 8 + b_lrow) * PITCH + kb + b_lcol]));
#pragma unroll
            for (int mi = 0; mi < 4; mi++)
#pragma unroll
                for (int ni = 0; ni < 4; ni++) mma_bf16(acc[mi][ni], A[mi], Bh[ni]);
            // pass 2: Ah x Bl
#pragma unroll
            for (int ni = 0; ni < 4; ni++)
                ldsm2(Bl[ni], sptr(&Bs_lo[(warp_n + ni * 8 + b_lrow) * PITCH + kb + b_lcol]));
#pragma unroll
            for (int mi = 0; mi < 4; mi++)
#pragma unroll
                for (int ni = 0; ni < 4; ni++) mma_bf16(acc[mi][ni], A[mi], Bl[ni]);
            // pass 3: Al x Bh
#pragma unroll
            for (int mi = 0; mi < 4; mi++)
                ldsm4(A[mi], sptr(&As_lo[(warp_m + mi * 16 + a_lrow) * PITCH + kb + a_lcol]));
#pragma unroll
            for (int mi = 0; mi < 4; mi++)
#pragma unroll
                for (int ni = 0; ni < 4; ni++) mma_bf16(acc[mi][ni], A[mi], Bh[ni]);
        }
    };

    const int KT = lda >> 5;
    load_stage(0, 0);
    asm volatile("cp.async.commit_group;" ::: "memory");
    for (int kt = 0; kt < KT; kt++) {
        if (kt + 1 < KT) {
            load_stage((kt + 1) & 1, (kt + 1) << 5);
            asm volatile("cp.async.commit_group;" ::: "memory");
            asm volatile("cp.async.wait_group 1;" ::: "memory");
        } else {
            asm volatile("cp.async.wait_group 0;" ::: "memory");
        }
        __syncthreads();
        compute(kt & 1);
        __syncthreads();
    }

    // epilogue
#pragma unroll
    for (int mi = 0; mi < 4; mi++) {
#pragma unroll
        for (int ni = 0; ni < 4; ni++) {
            int n0 = bcol + warp_n + ni * 8 + (lane & 3) * 2;
            float bx = bias ? bias[n0] : 0.f;
            float by = bias ? bias[n0 + 1] : 0.f;
            int m0 = brow + warp_m + mi * 16 + (lane >> 2);
#pragma unroll
            for (int h = 0; h < 2; h++) {
                int m = m0 + h * 8;
                if (m >= M) continue;
                float vx = acc[mi][ni][h * 2 + 0] + bx;
                float vy = acc[mi][ni][h * 2 + 1] + by;
                if (relu_c) { vx = fmaxf(vx, 0.f); vy = fmaxf(vy, 0.f); }
                if (out_split) {
                    __nv_bfloat16 h0 = __float2bfloat16(vx);
                    __nv_bfloat16 h1 = __float2bfloat16(vy);
                    __nv_bfloat162 hv; hv.x = h0; hv.y = h1;
                    __nv_bfloat162 lv;
                    lv.x = __float2bfloat16(vx - __bfloat162float(h0));
                    lv.y = __float2bfloat16(vy - __bfloat162float(h1));
                    *reinterpret_cast<__nv_bfloat162*>(&Chi[(size_t)m * Nc + n0]) = hv;
                    *reinterpret_cast<__nv_bfloat162*>(&Clo[(size_t)m * Nc + n0]) = lv;
                } else {
                    float2 v; v.x = vx; v.y = vy;
                    *reinterpret_cast<float2*>(&C[(size_t)m * Nc + n0]) = v;
                }
            }
        }
    }
}

// =====================================================================
// Fused LSTM step (R6, proven): gates = h_{t-1}@Whh^T (+xg_t+bhh), pointwise.
// =====================================================================
__global__ void __launch_bounds__(256, 2) lstm_step_kernel(
    const __nv_bfloat16* __restrict__ Ahi, const __nv_bfloat16* __restrict__ Alo,
    const __nv_bfloat16* __restrict__ Bhi, const __nv_bfloat16* __restrict__ Blo,
    const float* __restrict__ xg, const float* __restrict__ bhh,
    float* __restrict__ cst,
    __nv_bfloat16* __restrict__ Ohi, __nv_bfloat16* __restrict__ Olo,
    int M, int t)
{
    extern __shared__ __nv_bfloat16 smem2[];

    const int tid  = threadIdx.x;
    const int lane = tid & 31;
    const int warp = tid >> 5;
    const int warp_m = (warp >> 2) << 6;
    const int warp_n = (warp & 3) << 5;
    const int brow = blockIdx.y * 128;
    const int hc0  = blockIdx.x * 32;

    float acc[4][4][4];
#pragma unroll
    for (int i = 0; i < 4; i++)
#pragma unroll
        for (int j = 0; j < 4; j++)
#pragma unroll
            for (int v = 0; v < 4; v++) acc[i][j][v] = 0.f;

    const int l_row = tid >> 1;
    const int l_kc  = (tid & 1) << 4;
    const int gr  = brow + l_row;
    const bool okA = (gr < M);
    const int grc = okA ? gr : 0;
    const int b_gate = l_row >> 5;
    const int b_idx  = l_row & 31;
    const int gBrow  = b_gate * 256 + hc0 + b_idx;

    const int a_lrow = (lane & 7) + ((lane >> 3) & 1) * 8;
    const int a_lcol = (lane >> 4) * 8;
    const int b_lrow = lane & 7;
    const int b_lcol = ((lane >> 3) & 1) * 8;

    auto load_stage = [&](int s, int k0) {
        __nv_bfloat16* base = smem2 + s * 4 * BUFE;
        size_t aoff = (size_t)grc * ASTR + k0 + l_kc;
        size_t boff = (size_t)gBrow * HID + k0 + l_kc;
        int so = l_row * PITCH + l_kc;
        cpasync16(base + 0 * BUFE + so,     Ahi + aoff,     okA);
        cpasync16(base + 0 * BUFE + so + 8, Ahi + aoff + 8, okA);
        cpasync16(base + 1 * BUFE + so,     Alo + aoff,     okA);
        cpasync16(base + 1 * BUFE + so + 8, Alo + aoff + 8, okA);
        cpasync16(base + 2 * BUFE + so,     Bhi + boff,     true);
        cpasync16(base + 2 * BUFE + so + 8, Bhi + boff + 8, true);
        cpasync16(base + 3 * BUFE + so,     Blo + boff,     true);
        cpasync16(base + 3 * BUFE + so + 8, Blo + boff + 8, true);
    };

    auto compute = [&](int s) {
        __nv_bfloat16* As_hi = smem2 + (s * 4 + 0) * BUFE;
        __nv_bfloat16* As_lo = smem2 + (s * 4 + 1) * BUFE;
        __nv_bfloat16* Bs_hi = smem2 + (s * 4 + 2) * BUFE;
        __nv_bfloat16* Bs_lo = smem2 + (s * 4 + 3) * BUFE;
#pragma unroll
        for (int st = 0; st < 2; st++) {
            int kb = st * 16;
            uint32_t A[4][4], Bh[4][2], Bl[4][2];
#pragma unroll
            for (int mi = 0; mi < 4; mi++)
                ldsm4(A[mi], sptr(&As_hi[(warp_m + mi * 16 + a_lrow) * PITCH + kb + a_lcol]));
#pragma unroll
            for (int ni = 0; ni < 4; ni++)
                ldsm2(Bh[ni], sptr(&Bs_hi[(warp_n + ni * 8 + b_lrow) * PITCH + kb + b_lcol]));
#pragma unroll
            for (int mi = 0; mi < 4; mi++)
#pragma unroll
                for (int ni = 0; ni < 4; ni++) mma_bf16(acc[mi][ni], A[mi], Bh[ni]);
#pragma unroll
            for (int ni = 0; ni < 4; ni++)
                ldsm2(Bl[ni], sptr(&Bs_lo[(warp_n + ni * 8 + b_lrow) * PITCH + kb + b_lcol]));
#pragma unroll
            for (int mi = 0; mi < 4; mi++)
#pragma unroll
                for (int ni = 0; ni < 4; ni++) mma_bf16(acc[mi][ni], A[mi], Bl[ni]);
#pragma unroll
            for (int mi = 0; mi < 4; mi++)
                ldsm4(A[mi], sptr(&As_lo[(warp_m + mi * 16 + a_lrow) * PITCH + kb + a_lcol]));
#pragma unroll
            for (int mi = 0; mi < 4; mi++)
#pragma unroll
                for (int ni = 0; ni < 4; ni++) mma_bf16(acc[mi][ni], A[mi], Bh[ni]);
        }
    };

    const int KT = HID >> 5;
    load_stage(0, 0);
    asm volatile("cp.async.commit_group;" ::: "memory");
    for (int kt = 0; kt < KT; kt++) {
        if (kt + 1 < KT) {
            load_stage((kt + 1) & 1, (kt + 1) << 5);
            asm volatile("cp.async.commit_group;" ::: "memory");
            asm volatile("cp.async.wait_group 1;" ::: "memory");
        } else {
            asm volatile("cp.async.wait_group 0;" ::: "memory");
        }
        __syncthreads();
        compute(kt & 1);
        __syncthreads();
    }

    float* gsm = reinterpret_cast<float*>(smem2);
#pragma unroll
    for (int mi = 0; mi < 4; mi++) {
#pragma unroll
        for (int ni = 0; ni < 4; ni++) {
            int lc = warp_n + ni * 8 + (lane & 3) * 2;
            int r0 = warp_m + mi * 16 + (lane >> 2);
#pragma unroll
            for (int h = 0; h < 2; h++) {
                int r = r0 + h * 8;
                gsm[r * 132 + lc]     = acc[mi][ni][h * 2 + 0];
                gsm[r * 132 + lc + 1] = acc[mi][ni][h * 2 + 1];
            }
        }
    }
    __syncthreads();

    for (int idx = tid; idx < 128 * 32; idx += 256) {
        int row = idx >> 5;
        int col = idx & 31;
        int m = brow + row;
        if (m >= M) continue;
        int hc = hc0 + col;
        size_t xr = ((size_t)m * Tt + t) * G4;
        float gi = gsm[row * 132 +  0 + col] + xg[xr + hc]       + bhh[hc];
        float gf = gsm[row * 132 + 32 + col] + xg[xr + 256 + hc] + bhh[256 + hc];
        float gg = gsm[row * 132 + 64 + col] + xg[xr + 512 + hc] + bhh[512 + hc];
        float go = gsm[row * 132 + 96 + col] + xg[xr + 768 + hc] + bhh[768 + hc];
        size_t ci = (size_t)m * HID + hc;
        float cn = sigmoidf_(gf) * cst[ci] + sigmoidf_(gi) * tanhf(gg);
        float hn = sigmoidf_(go) * tanhf(cn);
        cst[ci] = cn;
        size_t ho = (size_t)m * ASTR + hc;
        __nv_bfloat16 hh = __float2bfloat16(hn);
        Ohi[ho] = hh;
        Olo[ho] = __float2bfloat16(hn - __bfloat162float(hh));
    }
}

__global__ void lstm_init_kernel(const float* __restrict__ xg, const float* __restrict__ bhh,
                                 float* __restrict__ cst,
                                 __nv_bfloat16* __restrict__ Ohi, __nv_bfloat16* __restrict__ Olo)
{
    size_t idx = (size_t)blockIdx.x * blockDim.x + threadIdx.x;
    if (idx >= (size_t)Nn * HID) return;
    size_t n = idx >> 8;
    int hc = (int)(idx & 255);
    size_t xr = n * Tt * (size_t)G4;
    float gi = xg[xr + hc]       + bhh[hc];
    float gg = xg[xr + 512 + hc] + bhh[512 + hc];
    float go = xg[xr + 768 + hc] + bhh[768 + hc];
    float cn = sigmoidf_(gi) * tanhf(gg);
    float hn = sigmoidf_(go) * tanhf(cn);
    cst[idx] = cn;
    size_t ho = n * ASTR + hc;
    __nv_bfloat16 hh = __float2bfloat16(hn);
    Ohi[ho] = hh;
    Olo[ho] = __float2bfloat16(hn - __bfloat162float(hh));
}

// ---------------- split / init kernels ----------------
__global__ void split_rows(const float* __restrict__ src,
                           __nv_bfloat16* __restrict__ hi, __nv_bfloat16* __restrict__ lo,
                           long long R, int C, int Cp, int relu)
{
    long long total = R * (Cp >> 2);
    long long stride = (long long)gridDim.x * blockDim.x;
    int gpr = Cp >> 2;
    for (long long g = (long long)blockIdx.x * blockDim.x + threadIdx.x; g < total; g += stride) {
        int gp = (int)(g % gpr);
        long long r = g / gpr;
        int c = gp << 2;
        float4 v = make_float4(0.f, 0.f, 0.f, 0.f);
        if (c + 3 < C) v = *reinterpret_cast<const float4*>(&src[r * C + c]);
        else if (c < C) {
            float tmp[4] = {0.f, 0.f, 0.f, 0.f};
            for (int e = 0; e < 4 && c + e < C; e++) tmp[e] = src[r * C + c + e];
            v.x = tmp[0]; v.y = tmp[1]; v.z = tmp[2]; v.w = tmp[3];
        }
        if (relu) {
            v.x = fmaxf(v.x, 0.f); v.y = fmaxf(v.y, 0.f);
            v.z = fmaxf(v.z, 0.f); v.w = fmaxf(v.w, 0.f);
        }
        float vv[4] = {v.x, v.y, v.z, v.w};
        __nv_bfloat16 h4[4], l4[4];
#pragma unroll
        for (int e = 0; e < 4; e++) {
            h4[e] = __float2bfloat16(vv[e]);
            l4[e] = __float2bfloat16(vv[e] - __bfloat162float(h4[e]));
        }
        *reinterpret_cast<uint2*>(&hi[r * Cp + c]) = *reinterpret_cast<uint2*>(h4);
        *reinterpret_cast<uint2*>(&lo[r * Cp + c]) = *reinterpret_cast<uint2*>(l4);
    }
}

__global__ void split_weights_all(const float* __restrict__ W1, const float* __restrict__ W2,
                                  const float* __restrict__ Wih0, const float* __restrict__ Whh0,
                                  const float* __restrict__ Wih1, const float* __restrict__ Whh1,
                                  const float* __restrict__ fcn_w,
                                  __nv_bfloat16* __restrict__ whi, __nv_bfloat16* __restrict__ wlo)
{
    int stride = gridDim.x * blockDim.x;
    for (int i = blockIdx.x * blockDim.x + threadIdx.x; i < (int)WSPLIT_SZ; i += stride) {
        float v;
        if (i < 32768) {                       // W1T [256,128] <- W1[128,256]
            int n = i >> 7, k = i & 127; v = W1[k * 256 + n];
        } else if (i < 65536) {                // W2T [128,256] <- W2[256,128]
            int j = i - 32768; int n = j >> 8, k = j & 255; v = W2[k * 128 + n];
        } else if (i < 229376) {               // WIH0 [1024,160] pad from [1024,148]
            int j = i - 65536; int r = j / DSEQP, c = j % DSEQP;
            v = (c < DSEQ) ? Wih0[r * DSEQ + c] : 0.f;
        } else if (i < 491520) {               // WHH0 [1024,256]
            v = Whh0[i - 229376];
        } else if (i < 753664) {               // WIH1 [1024,256]
            v = Wih1[i - 491520];
        } else if (i < 1015808) {              // WHH1 [1024,256]
            v = Whh1[i - 753664];
        } else {                               // FCNT [128,256] <- fcn_w[256,128]
            int j = i - 1015808; int n = j >> 8, k = j & 255; v = fcn_w[k * 128 + n];
        }
        __nv_bfloat16 h = __float2bfloat16(v);
        whi[i] = h;
        wlo[i] = __float2bfloat16(v - __bfloat162float(h));
    }
}

__global__ void zero_f4(float4* __restrict__ p, size_t n4)
{
    size_t stride = (size_t)gridDim.x * blockDim.x;
    for (size_t i = (size_t)blockIdx.x * blockDim.x + threadIdx.x; i < n4; i += stride)
        p[i] = make_float4(0.f, 0.f, 0.f, 0.f);
}

__global__ void init_seq(float* __restrict__ seq, const float* __restrict__ b2,
                         const float* __restrict__ raw, size_t total)
{
    size_t stride = (size_t)gridDim.x * blockDim.x;
    for (size_t i = (size_t)blockIdx.x * blockDim.x + threadIdx.x; i < total; i += stride) {
        int c = (int)(i % DSEQ);
        size_t nt = i / DSEQ;
        int t = (int)(nt % Tt);
        size_t n = nt / Tt;
        seq[i] = (c < H2C) ? b2[c]
                           : raw[(size_t)t * Nn * RAWC + n * RAWC + (c - H2C)];
    }
}

// ---------------- fp32 fallback GEMM (final out gemm, Nc=64) ----------------
template<int BM, int BN, int BK, int TM, int TN>
__global__ void sgemm_kernel(const float* __restrict__ A, const float* __restrict__ B,
                             float* __restrict__ C, const float* __restrict__ bias,
                             int M, int K, int Nc)
{
    __shared__ float As[BK][BM];
    __shared__ float Bs[BK][BN];
    const int tid = threadIdx.x;
    const int brow = blockIdx.y * BM;
    const int bcol = blockIdx.x * BN;
    const int trow = (tid / (BN / TN)) * TM;
    const int tcol = (tid % (BN / TN)) * TN;

    float acc[TM][TN];
#pragma unroll
    for (int i = 0; i < TM; i++)
#pragma unroll
        for (int j = 0; j < TN; j++) acc[i][j] = 0.f;

    for (int k0 = 0; k0 < K; k0 += BK) {
#pragma unroll
        for (int i = 0; i < (BM * BK) / 256; i++) {
            int l = tid + i * 256;
            int m = l / BK, k = l % BK;
            int gr = brow + m, gk = k0 + k;
            As[k][m] = (gr < M && gk < K) ? A[(size_t)gr * K + gk] : 0.f;
        }
#pragma unroll
        for (int i = 0; i < (BK * BN) / 256; i++) {
            int l = tid + i * 256;
            int k = l / BN, n = l % BN;
            int gk = k0 + k, gn = bcol + n;
            Bs[k][n] = (gk < K && gn < Nc) ? B[(size_t)gk * Nc + gn] : 0.f;
        }
        __syncthreads();
#pragma unroll
        for (int k = 0; k < BK; k++) {
            float ar[TM], br[TN];
#pragma unroll
            for (int i = 0; i < TM; i++) ar[i] = As[k][trow + i];
#pragma unroll
            for (int j = 0; j < TN; j++) br[j] = Bs[k][tcol + j];
#pragma unroll
            for (int i = 0; i < TM; i++)
#pragma unroll
                for (int j = 0; j < TN; j++) acc[i][j] = fmaf(ar[i], br[j], acc[i][j]);
        }
        __syncthreads();
    }
#pragma unroll
    for (int i = 0; i < TM; i++) {
        int gr = brow + trow + i;
        if (gr >= M) continue;
#pragma unroll
        for (int j = 0; j < TN; j++) {
            int gn = bcol + tcol + j;
            if (gn >= Nc) continue;
            float v = acc[i][j];
            if (bias) v += bias[gn];
            C[(size_t)gr * Nc + gn] = v;
        }
    }
}

// ---------------- SpMM scatter (128-col) ----------------
__global__ void spmm_scatter128(const float* __restrict__ src,
                                const int* __restrict__ erow, const int* __restrict__ ecol,
                                const float* __restrict__ ew,
                                float* __restrict__ dst,
                                int dst_ld, int dst_layout)
{
    long long warp = ((long long)blockIdx.x * blockDim.x + threadIdx.x) >> 5;
    int lane = threadIdx.x & 31;
    if (warp >= (long long)Tt * Ee) return;
    int t = (int)(warp / Ee);
    int e = (int)(warp % Ee);
    size_t eoff = (size_t)t * Ee + e;
    int r = erow[eoff];
    int c = ecol[eoff];
    float w = ew[eoff];
    const float* s = src + ((size_t)t * Nn + c) * 128;
    size_t doff = (dst_layout == 0) ? ((size_t)t * Nn + r) * (size_t)dst_ld
                                    : ((size_t)r * Tt + t) * (size_t)dst_ld;
    float* d = dst + doff;
    int j = lane << 2;
    float4 v = *reinterpret_cast<const float4*>(&s[j]);
    red4(&d[j], w * v.x, w * v.y, w * v.z, w * v.w);
}

// ---------------- attention pooling (reads split hseq chain) ----------------
__global__ void attention_pool(const __nv_bfloat16* __restrict__ hhi,
                               const __nv_bfloat16* __restrict__ hlo,
                               const float* __restrict__ att_w,
                               const float* __restrict__ att_b,
                               __nv_bfloat16* __restrict__ phi,
                               __nv_bfloat16* __restrict__ plo)
{
    __shared__ float hs[Tt * HID];
    __shared__ float aw[HID];
    __shared__ float red[HID];
    __shared__ float sc[Tt];
    int n = blockIdx.x;
    int tid = threadIdx.x;
    size_t base = (size_t)n * ASTR;
#pragma unroll
    for (int i = 0; i < Tt; i++)
        hs[i * HID + tid] = __bfloat162float(hhi[base + i * HID + tid]) +
                            __bfloat162float(hlo[base + i * HID + tid]);
    aw[tid] = att_w[tid];
    __syncthreads();
    float ab = att_b[0];
    for (int t = 0; t < Tt; t++) {
        red[tid] = hs[t * HID + tid] * aw[tid];
        __syncthreads();
        for (int s = HID / 2; s > 0; s >>= 1) {
            if (tid < s) red[tid] += red[tid + s];
            __syncthreads();
        }
        if (tid == 0) sc[t] = red[0] + ab;
        __syncthreads();
    }
    float mx = -1e30f;
#pragma unroll
    for (int t = 0; t < Tt; t++) mx = fmaxf(mx, sc[t]);
    float a[Tt], sum = 0.f;
#pragma unroll
    for (int t = 0; t < Tt; t++) { a[t] = expf(sc[t] - mx); sum += a[t]; }
    float p = 0.f;
#pragma unroll
    for (int t = 0; t < Tt; t++) p += a[t] * hs[t * HID + tid];
    p /= sum;
    __nv_bfloat16 h = __float2bfloat16(p);
    phi[(size_t)n * HID + tid] = h;
    plo[(size_t)n * HID + tid] = __float2bfloat16(p - __bfloat162float(h));
}

// ---------------- host wrappers ----------------
static inline void gemm_f32(const __nv_bfloat16* Ahi, const __nv_bfloat16* Alo,
                            const __nv_bfloat16* Bhi, const __nv_bfloat16* Blo,
                            float* C, const float* bias, int M, int lda, int Nc, int relu)
{
    dim3 grid(Nc / 128, (M + 127) / 128);
    mma_gemm_bf16<<<grid, 256, SHBYTES>>>(Ahi, Alo, Bhi, Blo, C, nullptr, nullptr,
                                          bias, M, lda, Nc, relu, 0);
}
static inline void gemm_sp(const __nv_bfloat16* Ahi, const __nv_bfloat16* Alo,
                           const __nv_bfloat16* Bhi, const __nv_bfloat16* Blo,
                           __nv_bfloat16* Chi, __nv_bfloat16* Clo,
                           const float* bias, int M, int lda, int Nc, int relu)
{
    dim3 grid(Nc / 128, (M + 127) / 128);
    mma_gemm_bf16<<<grid, 256, SHBYTES>>>(Ahi, Alo, Bhi, Blo, nullptr, Chi, Clo,
                                          bias, M, lda, Nc, relu, 1);
}

extern "C" void kernel_launch(void* const* d_in, const int* in_sizes, int n_in,
                              void* d_out, int out_size)
{
    const float* nodes = (const float*)d_in[0];
    const int*   erow  = (const int*)  d_in[1];
    const int*   ecol  = (const int*)  d_in[2];
    const float* ew    = (const float*)d_in[3];
    const float* raw   = (const float*)d_in[4];
    const float* W1    = (const float*)d_in[5];
    const float* b1    = (const float*)d_in[6];
    const float* W2    = (const float*)d_in[7];
    const float* b2    = (const float*)d_in[8];
    const float* Wih0  = (const float*)d_in[9];
    const float* Whh0  = (const float*)d_in[10];
    const float* bih0  = (const float*)d_in[11];
    const float* bhh0  = (const float*)d_in[12];
    const float* Wih1  = (const float*)d_in[13];
    const float* Whh1  = (const float*)d_in[14];
    const float* bih1  = (const float*)d_in[15];
    const float* bhh1  = (const float*)d_in[16];
    const float* att_w = (const float*)d_in[17];
    const float* att_b = (const float*)d_in[18];
    const float* fcn_w = (const float*)d_in[19];
    const float* fcn_b = (const float*)d_in[20];
    const float* out_w = (const float*)d_in[21];
    const float* out_b = (const float*)d_in[22];
    float* out = (float*)d_out;

    static bool attr_done = false;
    if (!attr_done) {
        cudaFuncSetAttribute(mma_gemm_bf16, cudaFuncAttributeMaxDynamicSharedMemorySize, SHBYTES);
        cudaFuncSetAttribute(lstm_step_kernel, cudaFuncAttributeMaxDynamicSharedMemorySize, SHBYTES);
        attr_done = true;
    }

    float *bufX, *seq, *xg, *cst, *z;
    __nv_bfloat16 *ahi, *alo, *bhi, *blo, *phi, *plo, *whi, *wlo;
    cudaGetSymbolAddress((void**)&bufX, g_bufX);
    cudaGetSymbolAddress((void**)&seq,  g_seq);
    cudaGetSymbolAddress((void**)&xg,   g_xg);
    cudaGetSymbolAddress((void**)&cst,  g_c);
    cudaGetSymbolAddress((void**)&z,    g_z);
    cudaGetSymbolAddress((void**)&ahi,  g_ahi);
    cudaGetSymbolAddress((void**)&alo,  g_alo);
    cudaGetSymbolAddress((void**)&bhi,  g_bhi);
    cudaGetSymbolAddress((void**)&blo,  g_blo);
    cudaGetSymbolAddress((void**)&phi,  g_phi);
    cudaGetSymbolAddress((void**)&plo,  g_plo);
    cudaGetSymbolAddress((void**)&whi,  g_whi);
    cudaGetSymbolAddress((void**)&wlo,  g_wlo);

    const int M = (int)NT;
    const long long sc_blocks = ((long long)Tt * Ee * 32 + 255) / 256;
    const dim3 lstm_grid(HID / 32, (Nn + 127) / 128);
    const int init_blocks = (int)(((size_t)Nn * HID + 255) / 256);

    // L1: all weight splits (one launch)
    split_weights_all<<<1024, 256>>>(W1, W2, Wih0, Whh0, Wih1, Whh1, fcn_w, whi, wlo);

    // L2: zero agg
    zero_f4<<<4096, 256>>>((float4*)bufX, NT * (size_t)FIN / 4);

    // L3: agg = spmm(nodes)
    spmm_scatter128<<<(unsigned)sc_blocks, 256>>>(nodes, erow, ecol, ew, bufX, FIN, 0);

    // L4: split agg
    split_rows<<<8192, 256>>>(bufX, ahi, alo, (long long)NT, FIN, FIN, 0);

    // L5: x = relu(agg @ W1 + b1) -> split
    gemm_sp(ahi, alo, whi + OFF_W1T, wlo + OFF_W1T, bhi, blo, b1, M, FIN, H1C, 1);

    // L6: support2 = x @ W2  <-- ncu capture lands here (-s 5 -c 1)
    gemm_f32(bhi, blo, whi + OFF_W2T, wlo + OFF_W2T, bufX, nullptr, M, H1C, H2C, 0);

    // seq = [spmm(support2)+b2 | raw]
    init_seq<<<8192, 256>>>(seq, b2, raw, NT * (size_t)DSEQ);
    spmm_scatter128<<<(unsigned)sc_blocks, 256>>>(bufX, erow, ecol, ew, seq, DSEQ, 1);

    // xg0 = seq @ Wih0^T + bih0
    split_rows<<<8192, 256>>>(seq, bhi, blo, (long long)NT, DSEQ, DSEQP, 0);
    gemm_f32(bhi, blo, whi + OFF_WIH0, wlo + OFF_WIH0, xg, bih0, M, DSEQP, G4, 0);

    // LSTM layer 0 -> split chain in ahi/alo
    lstm_init_kernel<<<init_blocks, 256>>>(xg, bhh0, cst, ahi, alo);
    for (int t = 1; t < Tt; t++) {
        lstm_step_kernel<<<lstm_grid, 256, SHBYTES>>>(
            ahi + (size_t)(t - 1) * HID, alo + (size_t)(t - 1) * HID,
            whi + OFF_WHH0, wlo + OFF_WHH0, xg, bhh0, cst,
            ahi + (size_t)t * HID, alo + (size_t)t * HID, Nn, t);
    }

    // xg1 = hseq0 @ Wih1^T + bih1
    gemm_f32(ahi, alo, whi + OFF_WIH1, wlo + OFF_WIH1, xg, bih1, M, HID, G4, 0);

    // LSTM layer 1 -> split chain (reused)
    lstm_init_kernel<<<init_blocks, 256>>>(xg, bhh1, cst, ahi, alo);
    for (int t = 1; t < Tt; t++) {
        lstm_step_kernel<<<lstm_grid, 256, SHBYTES>>>(
            ahi + (size_t)(t - 1) * HID, alo + (size_t)(t - 1) * HID,
            whi + OFF_WHH1, wlo + OFF_WHH1, xg, bhh1, cst,
            ahi + (size_t)t * HID, alo + (size_t)t * HID, Nn, t);
    }

    // attention pooling (reads split chain) -> split pooled
    attention_pool<<<Nn, HID>>>(ahi, alo, att_w, att_b, phi, plo);

    // z = relu(pooled @ fcn_w + fcn_b)
    gemm_f32(phi, plo, whi + OFF_FCNT, wlo + OFF_FCNT, z, fcn_b, Nn, HID, 128, 1);

    // out = z @ out_w + out_b
    {
        dim3 grid((OUTC + 63) / 64, (Nn + 63) / 64);
        sgemm_kernel<64, 64, 16, 4, 4><<<grid, 256>>>(z, out_w, out, out_b, Nn, 128, OUTC);
    }
}

// round 16
// speedup vs baseline: 1.0594x; 1.0016x over previous
#include <cuda_runtime.h>
#include <cuda_bf16.h>
#include <math.h>
#include <stdint.h>

// ---------------- problem constants ----------------
constexpr int Tt   = 12;
constexpr int Nn   = 30000;
constexpr int Ee   = 480000;
constexpr int FIN  = 128;
constexpr int H1C  = 256;
constexpr int H2C  = 128;
constexpr int RAWC = 20;
constexpr int HID  = 256;
constexpr int OUTC = 64;
constexpr int DSEQ = H2C + RAWC;   // 148
constexpr int DSEQP= 160;          // padded (multiple of 32)
constexpr int G4   = 4 * HID;      // 1024
constexpr int ASTR = Tt * HID;     // 3072
constexpr size_t NT = (size_t)Nn * Tt;  // 360000

// weight split buffer offsets (elements)
constexpr size_t OFF_W1T  = 0;         // [256,128]
constexpr size_t OFF_W2T  = 32768;     // [128,256]
constexpr size_t OFF_WIH0 = 65536;     // [1024,160]
constexpr size_t OFF_WHH0 = 229376;    // [1024,256]
constexpr size_t OFF_WIH1 = 491520;    // [1024,256]
constexpr size_t OFF_WHH1 = 753664;    // [1024,256]
constexpr size_t OFF_FCNT = 1015808;   // [128,256]
constexpr size_t WSPLIT_SZ= 1048576;

// ---------------- scratch ----------------
__device__ float g_bufX[NT * 256];        // agg nodes -> support2
__device__ float g_seq [NT * DSEQ];
__device__ float g_xg  [NT * (size_t)G4];
__device__ float g_c   [(size_t)Nn * HID];
__device__ float g_z   [(size_t)Nn * 128];
__device__ __nv_bfloat16 g_ahi[NT * 256]; // agg split -> hseq0 chain -> hseq1 chain
__device__ __nv_bfloat16 g_alo[NT * 256];
__device__ __nv_bfloat16 g_bhi[NT * 256]; // x split -> seq split
__device__ __nv_bfloat16 g_blo[NT * 256];
__device__ __nv_bfloat16 g_phi[(size_t)Nn * HID];
__device__ __nv_bfloat16 g_plo[(size_t)Nn * HID];
__device__ __nv_bfloat16 g_whi[WSPLIT_SZ];
__device__ __nv_bfloat16 g_wlo[WSPLIT_SZ];

// ---------------- helpers ----------------
__device__ __forceinline__ uint32_t sptr(const void* p) {
    return (uint32_t)__cvta_generic_to_shared(p);
}
__device__ __forceinline__ void ldsm4(uint32_t* r, uint32_t a) {
    asm volatile("ldmatrix.sync.aligned.m8n8.x4.shared.b16 {%0,%1,%2,%3}, [%4];"
                 : "=r"(r[0]), "=r"(r[1]), "=r"(r[2]), "=r"(r[3]) : "r"(a));
}
__device__ __forceinline__ void ldsm2(uint32_t* r, uint32_t a) {
    asm volatile("ldmatrix.sync.aligned.m8n8.x2.shared.b16 {%0,%1}, [%2];"
                 : "=r"(r[0]), "=r"(r[1]) : "r"(a));
}
__device__ __forceinline__ void mma_bf16(float* c, const uint32_t* a, const uint32_t* b) {
    asm volatile("mma.sync.aligned.m16n8k16.row.col.f32.bf16.bf16.f32 "
                 "{%0,%1,%2,%3}, {%4,%5,%6,%7}, {%8,%9}, {%0,%1,%2,%3};"
                 : "+f"(c[0]), "+f"(c[1]), "+f"(c[2]), "+f"(c[3])
                 : "r"(a[0]), "r"(a[1]), "r"(a[2]), "r"(a[3]), "r"(b[0]), "r"(b[1]));
}
__device__ __forceinline__ void cpasync16(void* dst, const void* src, bool pred) {
    int sz = pred ? 16 : 0;
    asm volatile("cp.async.cg.shared.global [%0], [%1], 16, %2;"
                 :: "r"(sptr(dst)), "l"(src), "r"(sz));
}
__device__ __forceinline__ void red4(float* addr, float x, float y, float z, float w) {
    asm volatile("red.global.add.v4.f32 [%0], {%1,%2,%3,%4};"
                 :: "l"(addr), "f"(x), "f"(y), "f"(z), "f"(w) : "memory");
}
__device__ __forceinline__ float sigmoidf_(float x) { return 1.f / (1.f + expf(-x)); }

#define PITCH 40
#define BUFE  (128 * PITCH)
#define SHBYTES (2 * 4 * BUFE * 2)   // 81920

// =====================================================================
// R6-proven GEMM: 128x128 block, 8 warps (2m x 4n), warp 64x32,
// 3-pass bf16 split, 2-stage cp.async, 2 blocks/SM.
// A:[M,lda] split row-major; B:[Nc,lda] split (B^T). Nc % 128 == 0.
// =====================================================================
__global__ void __launch_bounds__(256, 2) mma_gemm_bf16(
    const __nv_bfloat16* __restrict__ Ahi, const __nv_bfloat16* __restrict__ Alo,
    const __nv_bfloat16* __restrict__ Bhi, const __nv_bfloat16* __restrict__ Blo,
    float* __restrict__ C, __nv_bfloat16* __restrict__ Chi, __nv_bfloat16* __restrict__ Clo,
    const float* __restrict__ bias,
    int M, int lda, int Nc, int relu_c, int out_split)
{
    extern __shared__ __nv_bfloat16 smem[];

    const int tid  = threadIdx.x;
    const int lane = tid & 31;
    const int warp = tid >> 5;
    const int warp_m = (warp >> 2) << 6;  // 0 or 64
    const int warp_n = (warp & 3) << 5;   // 0,32,64,96
    const int brow = blockIdx.y * 128;
    const int bcol = blockIdx.x * 128;

    float acc[4][4][4];
#pragma unroll
    for (int i = 0; i < 4; i++)
#pragma unroll
        for (int j = 0; j < 4; j++)
#pragma unroll
            for (int v = 0; v < 4; v++) acc[i][j][v] = 0.f;

    const int l_row = tid >> 1;
    const int l_kc  = (tid & 1) << 4;
    const int gr  = brow + l_row;
    const bool okA = (gr < M);
    const int grc = okA ? gr : 0;
    const int gn  = bcol + l_row;

    const int a_lrow = (lane & 7) + ((lane >> 3) & 1) * 8;
    const int a_lcol = (lane >> 4) * 8;
    const int b_lrow = lane & 7;
    const int b_lcol = ((lane >> 3) & 1) * 8;

    auto load_stage = [&](int s, int k0) {
        __nv_bfloat16* base = smem + s * 4 * BUFE;
        size_t aoff = (size_t)grc * lda + k0 + l_kc;
        size_t boff = (size_t)gn  * lda + k0 + l_kc;
        int so = l_row * PITCH + l_kc;
        cpasync16(base + 0 * BUFE + so,     Ahi + aoff,     okA);
        cpasync16(base + 0 * BUFE + so + 8, Ahi + aoff + 8, okA);
        cpasync16(base + 1 * BUFE + so,     Alo + aoff,     okA);
        cpasync16(base + 1 * BUFE + so + 8, Alo + aoff + 8, okA);
        cpasync16(base + 2 * BUFE + so,     Bhi + boff,     true);
        cpasync16(base + 2 * BUFE + so + 8, Bhi + boff + 8, true);
        cpasync16(base + 3 * BUFE + so,     Blo + boff,     true);
        cpasync16(base + 3 * BUFE + so + 8, Blo + boff + 8, true);
    };

    auto compute = [&](int s) {
        __nv_bfloat16* As_hi = smem + (s * 4 + 0) * BUFE;
        __nv_bfloat16* As_lo = smem + (s * 4 + 1) * BUFE;
        __nv_bfloat16* Bs_hi = smem + (s * 4 + 2) * BUFE;
        __nv_bfloat16* Bs_lo = smem + (s * 4 + 3) * BUFE;
#pragma unroll
        for (int st = 0; st < 2; st++) {
            int kb = st * 16;
            uint32_t A[4][4], Bh[4][2], Bl[4][2];
            // pass 1: Ah x Bh
#pragma unroll
            for (int mi = 0; mi < 4; mi++)
                ldsm4(A[mi], sptr(&As_hi[(warp_m + mi * 16 + a_lrow) * PITCH + kb + a_lcol]));
#pragma unroll
            for (int ni = 0; ni < 4; ni++)
                ldsm2(Bh[ni], sptr(&Bs_hi[(warp_n + ni * 8 + b_lrow) * PITCH + kb + b_lcol]));
#pragma unroll
            for (int mi = 0; mi < 4; mi++)
#pragma unroll
                for (int ni = 0; ni < 4; ni++) mma_bf16(acc[mi][ni], A[mi], Bh[ni]);
            // pass 2: Ah x Bl
#pragma unroll
            for (int ni = 0; ni < 4; ni++)
                ldsm2(Bl[ni], sptr(&Bs_lo[(warp_n + ni * 8 + b_lrow) * PITCH + kb + b_lcol]));
#pragma unroll
            for (int mi = 0; mi < 4; mi++)
#pragma unroll
                for (int ni = 0; ni < 4; ni++) mma_bf16(acc[mi][ni], A[mi], Bl[ni]);
            // pass 3: Al x Bh
#pragma unroll
            for (int mi = 0; mi < 4; mi++)
                ldsm4(A[mi], sptr(&As_lo[(warp_m + mi * 16 + a_lrow) * PITCH + kb + a_lcol]));
#pragma unroll
            for (int mi = 0; mi < 4; mi++)
#pragma unroll
                for (int ni = 0; ni < 4; ni++) mma_bf16(acc[mi][ni], A[mi], Bh[ni]);
        }
    };

    const int KT = lda >> 5;
    load_stage(0, 0);
    asm volatile("cp.async.commit_group;" ::: "memory");
    for (int kt = 0; kt < KT; kt++) {
        if (kt + 1 < KT) {
            load_stage((kt + 1) & 1, (kt + 1) << 5);
            asm volatile("cp.async.commit_group;" ::: "memory");
            asm volatile("cp.async.wait_group 1;" ::: "memory");
        } else {
            asm volatile("cp.async.wait_group 0;" ::: "memory");
        }
        __syncthreads();
        compute(kt & 1);
        __syncthreads();
    }

    // epilogue
#pragma unroll
    for (int mi = 0; mi < 4; mi++) {
#pragma unroll
        for (int ni = 0; ni < 4; ni++) {
            int n0 = bcol + warp_n + ni * 8 + (lane & 3) * 2;
            float bx = bias ? bias[n0] : 0.f;
            float by = bias ? bias[n0 + 1] : 0.f;
            int m0 = brow + warp_m + mi * 16 + (lane >> 2);
#pragma unroll
            for (int h = 0; h < 2; h++) {
                int m = m0 + h * 8;
                if (m >= M) continue;
                float vx = acc[mi][ni][h * 2 + 0] + bx;
                float vy = acc[mi][ni][h * 2 + 1] + by;
                if (relu_c) { vx = fmaxf(vx, 0.f); vy = fmaxf(vy, 0.f); }
                if (out_split) {
                    __nv_bfloat16 h0 = __float2bfloat16(vx);
                    __nv_bfloat16 h1 = __float2bfloat16(vy);
                    __nv_bfloat162 hv; hv.x = h0; hv.y = h1;
                    __nv_bfloat162 lv;
                    lv.x = __float2bfloat16(vx - __bfloat162float(h0));
                    lv.y = __float2bfloat16(vy - __bfloat162float(h1));
                    *reinterpret_cast<__nv_bfloat162*>(&Chi[(size_t)m * Nc + n0]) = hv;
                    *reinterpret_cast<__nv_bfloat162*>(&Clo[(size_t)m * Nc + n0]) = lv;
                } else {
                    float2 v; v.x = vx; v.y = vy;
                    *reinterpret_cast<float2*>(&C[(size_t)m * Nc + n0]) = v;
                }
            }
        }
    }
}

// =====================================================================
// Fused LSTM step (R6, proven): gates = h_{t-1}@Whh^T (+xg_t+bhh), pointwise.
// =====================================================================
__global__ void __launch_bounds__(256, 2) lstm_step_kernel(
    const __nv_bfloat16* __restrict__ Ahi, const __nv_bfloat16* __restrict__ Alo,
    const __nv_bfloat16* __restrict__ Bhi, const __nv_bfloat16* __restrict__ Blo,
    const float* __restrict__ xg, const float* __restrict__ bhh,
    float* __restrict__ cst,
    __nv_bfloat16* __restrict__ Ohi, __nv_bfloat16* __restrict__ Olo,
    int M, int t)
{
    extern __shared__ __nv_bfloat16 smem2[];

    const int tid  = threadIdx.x;
    const int lane = tid & 31;
    const int warp = tid >> 5;
    const int warp_m = (warp >> 2) << 6;
    const int warp_n = (warp & 3) << 5;
    const int brow = blockIdx.y * 128;
    const int hc0  = blockIdx.x * 32;

    float acc[4][4][4];
#pragma unroll
    for (int i = 0; i < 4; i++)
#pragma unroll
        for (int j = 0; j < 4; j++)
#pragma unroll
            for (int v = 0; v < 4; v++) acc[i][j][v] = 0.f;

    const int l_row = tid >> 1;
    const int l_kc  = (tid & 1) << 4;
    const int gr  = brow + l_row;
    const bool okA = (gr < M);
    const int grc = okA ? gr : 0;
    const int b_gate = l_row >> 5;
    const int b_idx  = l_row & 31;
    const int gBrow  = b_gate * 256 + hc0 + b_idx;

    const int a_lrow = (lane & 7) + ((lane >> 3) & 1) * 8;
    const int a_lcol = (lane >> 4) * 8;
    const int b_lrow = lane & 7;
    const int b_lcol = ((lane >> 3) & 1) * 8;

    auto load_stage = [&](int s, int k0) {
        __nv_bfloat16* base = smem2 + s * 4 * BUFE;
        size_t aoff = (size_t)grc * ASTR + k0 + l_kc;
        size_t boff = (size_t)gBrow * HID + k0 + l_kc;
        int so = l_row * PITCH + l_kc;
        cpasync16(base + 0 * BUFE + so,     Ahi + aoff,     okA);
        cpasync16(base + 0 * BUFE + so + 8, Ahi + aoff + 8, okA);
        cpasync16(base + 1 * BUFE + so,     Alo + aoff,     okA);
        cpasync16(base + 1 * BUFE + so + 8, Alo + aoff + 8, okA);
        cpasync16(base + 2 * BUFE + so,     Bhi + boff,     true);
        cpasync16(base + 2 * BUFE + so + 8, Bhi + boff + 8, true);
        cpasync16(base + 3 * BUFE + so,     Blo + boff,     true);
        cpasync16(base + 3 * BUFE + so + 8, Blo + boff + 8, true);
    };

    auto compute = [&](int s) {
        __nv_bfloat16* As_hi = smem2 + (s * 4 + 0) * BUFE;
        __nv_bfloat16* As_lo = smem2 + (s * 4 + 1) * BUFE;
        __nv_bfloat16* Bs_hi = smem2 + (s * 4 + 2) * BUFE;
        __nv_bfloat16* Bs_lo = smem2 + (s * 4 + 3) * BUFE;
#pragma unroll
        for (int st = 0; st < 2; st++) {
            int kb = st * 16;
            uint32_t A[4][4], Bh[4][2], Bl[4][2];
#pragma unroll
            for (int mi = 0; mi < 4; mi++)
                ldsm4(A[mi], sptr(&As_hi[(warp_m + mi * 16 + a_lrow) * PITCH + kb + a_lcol]));
#pragma unroll
            for (int ni = 0; ni < 4; ni++)
                ldsm2(Bh[ni], sptr(&Bs_hi[(warp_n + ni * 8 + b_lrow) * PITCH + kb + b_lcol]));
#pragma unroll
            for (int mi = 0; mi < 4; mi++)
#pragma unroll
                for (int ni = 0; ni < 4; ni++) mma_bf16(acc[mi][ni], A[mi], Bh[ni]);
#pragma unroll
            for (int ni = 0; ni < 4; ni++)
                ldsm2(Bl[ni], sptr(&Bs_lo[(warp_n + ni * 8 + b_lrow) * PITCH + kb + b_lcol]));
#pragma unroll
            for (int mi = 0; mi < 4; mi++)
#pragma unroll
                for (int ni = 0; ni < 4; ni++) mma_bf16(acc[mi][ni], A[mi], Bl[ni]);
#pragma unroll
            for (int mi = 0; mi < 4; mi++)
                ldsm4(A[mi], sptr(&As_lo[(warp_m + mi * 16 + a_lrow) * PITCH + kb + a_lcol]));
#pragma unroll
            for (int mi = 0; mi < 4; mi++)
#pragma unroll
                for (int ni = 0; ni < 4; ni++) mma_bf16(acc[mi][ni], A[mi], Bh[ni]);
        }
    };

    const int KT = HID >> 5;
    load_stage(0, 0);
    asm volatile("cp.async.commit_group;" ::: "memory");
    for (int kt = 0; kt < KT; kt++) {
        if (kt + 1 < KT) {
            load_stage((kt + 1) & 1, (kt + 1) << 5);
            asm volatile("cp.async.commit_group;" ::: "memory");
            asm volatile("cp.async.wait_group 1;" ::: "memory");
        } else {
            asm volatile("cp.async.wait_group 0;" ::: "memory");
        }
        __syncthreads();
        compute(kt & 1);
        __syncthreads();
    }

    float* gsm = reinterpret_cast<float*>(smem2);
#pragma unroll
    for (int mi = 0; mi < 4; mi++) {
#pragma unroll
        for (int ni = 0; ni < 4; ni++) {
            int lc = warp_n + ni * 8 + (lane & 3) * 2;
            int r0 = warp_m + mi * 16 + (lane >> 2);
#pragma unroll
            for (int h = 0; h < 2; h++) {
                int r = r0 + h * 8;
                gsm[r * 132 + lc]     = acc[mi][ni][h * 2 + 0];
                gsm[r * 132 + lc + 1] = acc[mi][ni][h * 2 + 1];
            }
        }
    }
    __syncthreads();

    for (int idx = tid; idx < 128 * 32; idx += 256) {
        int row = idx >> 5;
        int col = idx & 31;
        int m = brow + row;
        if (m >= M) continue;
        int hc = hc0 + col;
        size_t xr = ((size_t)m * Tt + t) * G4;
        float gi = gsm[row * 132 +  0 + col] + xg[xr + hc]       + bhh[hc];
        float gf = gsm[row * 132 + 32 + col] + xg[xr + 256 + hc] + bhh[256 + hc];
        float gg = gsm[row * 132 + 64 + col] + xg[xr + 512 + hc] + bhh[512 + hc];
        float go = gsm[row * 132 + 96 + col] + xg[xr + 768 + hc] + bhh[768 + hc];
        size_t ci = (size_t)m * HID + hc;
        float cn = sigmoidf_(gf) * cst[ci] + sigmoidf_(gi) * tanhf(gg);
        float hn = sigmoidf_(go) * tanhf(cn);
        cst[ci] = cn;
        size_t ho = (size_t)m * ASTR + hc;
        __nv_bfloat16 hh = __float2bfloat16(hn);
        Ohi[ho] = hh;
        Olo[ho] = __float2bfloat16(hn - __bfloat162float(hh));
    }
}

__global__ void lstm_init_kernel(const float* __restrict__ xg, const float* __restrict__ bhh,
                                 float* __restrict__ cst,
                                 __nv_bfloat16* __restrict__ Ohi, __nv_bfloat16* __restrict__ Olo)
{
    size_t idx = (size_t)blockIdx.x * blockDim.x + threadIdx.x;
    if (idx >= (size_t)Nn * HID) return;
    size_t n = idx >> 8;
    int hc = (int)(idx & 255);
    size_t xr = n * Tt * (size_t)G4;
    float gi = xg[xr + hc]       + bhh[hc];
    float gg = xg[xr + 512 + hc] + bhh[512 + hc];
    float go = xg[xr + 768 + hc] + bhh[768 + hc];
    float cn = sigmoidf_(gi) * tanhf(gg);
    float hn = sigmoidf_(go) * tanhf(cn);
    cst[idx] = cn;
    size_t ho = n * ASTR + hc;
    __nv_bfloat16 hh = __float2bfloat16(hn);
    Ohi[ho] = hh;
    Olo[ho] = __float2bfloat16(hn - __bfloat162float(hh));
}

// ---------------- split / init kernels ----------------
__global__ void split_rows(const float* __restrict__ src,
                           __nv_bfloat16* __restrict__ hi, __nv_bfloat16* __restrict__ lo,
                           long long R, int C, int Cp, int relu)
{
    long long total = R * (Cp >> 2);
    long long stride = (long long)gridDim.x * blockDim.x;
    int gpr = Cp >> 2;
    for (long long g = (long long)blockIdx.x * blockDim.x + threadIdx.x; g < total; g += stride) {
        int gp = (int)(g % gpr);
        long long r = g / gpr;
        int c = gp << 2;
        float4 v = make_float4(0.f, 0.f, 0.f, 0.f);
        if (c + 3 < C) v = *reinterpret_cast<const float4*>(&src[r * C + c]);
        else if (c < C) {
            float tmp[4] = {0.f, 0.f, 0.f, 0.f};
            for (int e = 0; e < 4 && c + e < C; e++) tmp[e] = src[r * C + c + e];
            v.x = tmp[0]; v.y = tmp[1]; v.z = tmp[2]; v.w = tmp[3];
        }
        if (relu) {
            v.x = fmaxf(v.x, 0.f); v.y = fmaxf(v.y, 0.f);
            v.z = fmaxf(v.z, 0.f); v.w = fmaxf(v.w, 0.f);
        }
        float vv[4] = {v.x, v.y, v.z, v.w};
        __nv_bfloat16 h4[4], l4[4];
#pragma unroll
        for (int e = 0; e < 4; e++) {
            h4[e] = __float2bfloat16(vv[e]);
            l4[e] = __float2bfloat16(vv[e] - __bfloat162float(h4[e]));
        }
        *reinterpret_cast<uint2*>(&hi[r * Cp + c]) = *reinterpret_cast<uint2*>(h4);
        *reinterpret_cast<uint2*>(&lo[r * Cp + c]) = *reinterpret_cast<uint2*>(l4);
    }
}

__global__ void split_weights_all(const float* __restrict__ W1, const float* __restrict__ W2,
                                  const float* __restrict__ Wih0, const float* __restrict__ Whh0,
                                  const float* __restrict__ Wih1, const float* __restrict__ Whh1,
                                  const float* __restrict__ fcn_w,
                                  __nv_bfloat16* __restrict__ whi, __nv_bfloat16* __restrict__ wlo)
{
    int stride = gridDim.x * blockDim.x;
    for (int i = blockIdx.x * blockDim.x + threadIdx.x; i < (int)WSPLIT_SZ; i += stride) {
        float v;
        if (i < 32768) {                       // W1T [256,128] <- W1[128,256]
            int n = i >> 7, k = i & 127; v = W1[k * 256 + n];
        } else if (i < 65536) {                // W2T [128,256] <- W2[256,128]
            int j = i - 32768; int n = j >> 8, k = j & 255; v = W2[k * 128 + n];
        } else if (i < 229376) {               // WIH0 [1024,160] pad from [1024,148]
            int j = i - 65536; int r = j / DSEQP, c = j % DSEQP;
            v = (c < DSEQ) ? Wih0[r * DSEQ + c] : 0.f;
        } else if (i < 491520) {               // WHH0 [1024,256]
            v = Whh0[i - 229376];
        } else if (i < 753664) {               // WIH1 [1024,256]
            v = Wih1[i - 491520];
        } else if (i < 1015808) {              // WHH1 [1024,256]
            v = Whh1[i - 753664];
        } else {                               // FCNT [128,256] <- fcn_w[256,128]
            int j = i - 1015808; int n = j >> 8, k = j & 255; v = fcn_w[k * 128 + n];
        }
        __nv_bfloat16 h = __float2bfloat16(v);
        whi[i] = h;
        wlo[i] = __float2bfloat16(v - __bfloat162float(h));
    }
}

__global__ void zero_f4(float4* __restrict__ p, size_t n4)
{
    size_t stride = (size_t)gridDim.x * blockDim.x;
    for (size_t i = (size_t)blockIdx.x * blockDim.x + threadIdx.x; i < n4; i += stride)
        p[i] = make_float4(0.f, 0.f, 0.f, 0.f);
}

__global__ void init_seq(float* __restrict__ seq, const float* __restrict__ b2,
                         const float* __restrict__ raw, size_t total)
{
    size_t stride = (size_t)gridDim.x * blockDim.x;
    for (size_t i = (size_t)blockIdx.x * blockDim.x + threadIdx.x; i < total; i += stride) {
        int c = (int)(i % DSEQ);
        size_t nt = i / DSEQ;
        int t = (int)(nt % Tt);
        size_t n = nt / Tt;
        seq[i] = (c < H2C) ? b2[c]
                           : raw[(size_t)t * Nn * RAWC + n * RAWC + (c - H2C)];
    }
}

// ---------------- fp32 fallback GEMM (final out gemm, Nc=64) ----------------
template<int BM, int BN, int BK, int TM, int TN>
__global__ void sgemm_kernel(const float* __restrict__ A, const float* __restrict__ B,
                             float* __restrict__ C, const float* __restrict__ bias,
                             int M, int K, int Nc)
{
    __shared__ float As[BK][BM];
    __shared__ float Bs[BK][BN];
    const int tid = threadIdx.x;
    const int brow = blockIdx.y * BM;
    const int bcol = blockIdx.x * BN;
    const int trow = (tid / (BN / TN)) * TM;
    const int tcol = (tid % (BN / TN)) * TN;

    float acc[TM][TN];
#pragma unroll
    for (int i = 0; i < TM; i++)
#pragma unroll
        for (int j = 0; j < TN; j++) acc[i][j] = 0.f;

    for (int k0 = 0; k0 < K; k0 += BK) {
#pragma unroll
        for (int i = 0; i < (BM * BK) / 256; i++) {
            int l = tid + i * 256;
            int m = l / BK, k = l % BK;
            int gr = brow + m, gk = k0 + k;
            As[k][m] = (gr < M && gk < K) ? A[(size_t)gr * K + gk] : 0.f;
        }
#pragma unroll
        for (int i = 0; i < (BK * BN) / 256; i++) {
            int l = tid + i * 256;
            int k = l / BN, n = l % BN;
            int gk = k0 + k, gn = bcol + n;
            Bs[k][n] = (gk < K && gn < Nc) ? B[(size_t)gk * Nc + gn] : 0.f;
        }
        __syncthreads();
#pragma unroll
        for (int k = 0; k < BK; k++) {
            float ar[TM], br[TN];
#pragma unroll
            for (int i = 0; i < TM; i++) ar[i] = As[k][trow + i];
#pragma unroll
            for (int j = 0; j < TN; j++) br[j] = Bs[k][tcol + j];
#pragma unroll
            for (int i = 0; i < TM; i++)
#pragma unroll
                for (int j = 0; j < TN; j++) acc[i][j] = fmaf(ar[i], br[j], acc[i][j]);
        }
        __syncthreads();
    }
#pragma unroll
    for (int i = 0; i < TM; i++) {
        int gr = brow + trow + i;
        if (gr >= M) continue;
#pragma unroll
        for (int j = 0; j < TN; j++) {
            int gn = bcol + tcol + j;
            if (gn >= Nc) continue;
            float v = acc[i][j];
            if (bias) v += bias[gn];
            C[(size_t)gr * Nc + gn] = v;
        }
    }
}

// ---------------- SpMM scatter (128-col) ----------------
__global__ void spmm_scatter128(const float* __restrict__ src,
                                const int* __restrict__ erow, const int* __restrict__ ecol,
                                const float* __restrict__ ew,
                                float* __restrict__ dst,
                                int dst_ld, int dst_layout)
{
    long long warp = ((long long)blockIdx.x * blockDim.x + threadIdx.x) >> 5;
    int lane = threadIdx.x & 31;
    if (warp >= (long long)Tt * Ee) return;
    int t = (int)(warp / Ee);
    int e = (int)(warp % Ee);
    size_t eoff = (size_t)t * Ee + e;
    int r = erow[eoff];
    int c = ecol[eoff];
    float w = ew[eoff];
    const float* s = src + ((size_t)t * Nn + c) * 128;
    size_t doff = (dst_layout == 0) ? ((size_t)t * Nn + r) * (size_t)dst_ld
                                    : ((size_t)r * Tt + t) * (size_t)dst_ld;
    float* d = dst + doff;
    int j = lane << 2;
    float4 v = *reinterpret_cast<const float4*>(&s[j]);
    red4(&d[j], w * v.x, w * v.y, w * v.z, w * v.w);
}

// ---------------- attention pooling (reads split hseq chain) ----------------
__global__ void attention_pool(const __nv_bfloat16* __restrict__ hhi,
                               const __nv_bfloat16* __restrict__ hlo,
                               const float* __restrict__ att_w,
                               const float* __restrict__ att_b,
                               __nv_bfloat16* __restrict__ phi,
                               __nv_bfloat16* __restrict__ plo)
{
    __shared__ float hs[Tt * HID];
    __shared__ float aw[HID];
    __shared__ float red[HID];
    __shared__ float sc[Tt];
    int n = blockIdx.x;
    int tid = threadIdx.x;
    size_t base = (size_t)n * ASTR;
#pragma unroll
    for (int i = 0; i < Tt; i++)
        hs[i * HID + tid] = __bfloat162float(hhi[base + i * HID + tid]) +
                            __bfloat162float(hlo[base + i * HID + tid]);
    aw[tid] = att_w[tid];
    __syncthreads();
    float ab = att_b[0];
    for (int t = 0; t < Tt; t++) {
        red[tid] = hs[t * HID + tid] * aw[tid];
        __syncthreads();
        for (int s = HID / 2; s > 0; s >>= 1) {
            if (tid < s) red[tid] += red[tid + s];
            __syncthreads();
        }
        if (tid == 0) sc[t] = red[0] + ab;
        __syncthreads();
    }
    float mx = -1e30f;
#pragma unroll
    for (int t = 0; t < Tt; t++) mx = fmaxf(mx, sc[t]);
    float a[Tt], sum = 0.f;
#pragma unroll
    for (int t = 0; t < Tt; t++) { a[t] = expf(sc[t] - mx); sum += a[t]; }
    float p = 0.f;
#pragma unroll
    for (int t = 0; t < Tt; t++) p += a[t] * hs[t * HID + tid];
    p /= sum;
    __nv_bfloat16 h = __float2bfloat16(p);
    phi[(size_t)n * HID + tid] = h;
    plo[(size_t)n * HID + tid] = __float2bfloat16(p - __bfloat162float(h));
}

// ---------------- host wrappers ----------------
static inline void gemm_f32(const __nv_bfloat16* Ahi, const __nv_bfloat16* Alo,
                            const __nv_bfloat16* Bhi, const __nv_bfloat16* Blo,
                            float* C, const float* bias, int M, int lda, int Nc, int relu)
{
    dim3 grid(Nc / 128, (M + 127) / 128);
    mma_gemm_bf16<<<grid, 256, SHBYTES>>>(Ahi, Alo, Bhi, Blo, C, nullptr, nullptr,
                                          bias, M, lda, Nc, relu, 0);
}
static inline void gemm_sp(const __nv_bfloat16* Ahi, const __nv_bfloat16* Alo,
                           const __nv_bfloat16* Bhi, const __nv_bfloat16* Blo,
                           __nv_bfloat16* Chi, __nv_bfloat16* Clo,
                           const float* bias, int M, int lda, int Nc, int relu)
{
    dim3 grid(Nc / 128, (M + 127) / 128);
    mma_gemm_bf16<<<grid, 256, SHBYTES>>>(Ahi, Alo, Bhi, Blo, nullptr, Chi, Clo,
                                          bias, M, lda, Nc, relu, 1);
}

extern "C" void kernel_launch(void* const* d_in, const int* in_sizes, int n_in,
                              void* d_out, int out_size)
{
    const float* nodes = (const float*)d_in[0];
    const int*   erow  = (const int*)  d_in[1];
    const int*   ecol  = (const int*)  d_in[2];
    const float* ew    = (const float*)d_in[3];
    const float* raw   = (const float*)d_in[4];
    const float* W1    = (const float*)d_in[5];
    const float* b1    = (const float*)d_in[6];
    const float* W2    = (const float*)d_in[7];
    const float* b2    = (const float*)d_in[8];
    const float* Wih0  = (const float*)d_in[9];
    const float* Whh0  = (const float*)d_in[10];
    const float* bih0  = (const float*)d_in[11];
    const float* bhh0  = (const float*)d_in[12];
    const float* Wih1  = (const float*)d_in[13];
    const float* Whh1  = (const float*)d_in[14];
    const float* bih1  = (const float*)d_in[15];
    const float* bhh1  = (const float*)d_in[16];
    const float* att_w = (const float*)d_in[17];
    const float* att_b = (const float*)d_in[18];
    const float* fcn_w = (const float*)d_in[19];
    const float* fcn_b = (const float*)d_in[20];
    const float* out_w = (const float*)d_in[21];
    const float* out_b = (const float*)d_in[22];
    float* out = (float*)d_out;

    static bool attr_done = false;
    if (!attr_done) {
        cudaFuncSetAttribute(mma_gemm_bf16, cudaFuncAttributeMaxDynamicSharedMemorySize, SHBYTES);
        cudaFuncSetAttribute(lstm_step_kernel, cudaFuncAttributeMaxDynamicSharedMemorySize, SHBYTES);
        attr_done = true;
    }

    float *bufX, *seq, *xg, *cst, *z;
    __nv_bfloat16 *ahi, *alo, *bhi, *blo, *phi, *plo, *whi, *wlo;
    cudaGetSymbolAddress((void**)&bufX, g_bufX);
    cudaGetSymbolAddress((void**)&seq,  g_seq);
    cudaGetSymbolAddress((void**)&xg,   g_xg);
    cudaGetSymbolAddress((void**)&cst,  g_c);
    cudaGetSymbolAddress((void**)&z,    g_z);
    cudaGetSymbolAddress((void**)&ahi,  g_ahi);
    cudaGetSymbolAddress((void**)&alo,  g_alo);
    cudaGetSymbolAddress((void**)&bhi,  g_bhi);
    cudaGetSymbolAddress((void**)&blo,  g_blo);
    cudaGetSymbolAddress((void**)&phi,  g_phi);
    cudaGetSymbolAddress((void**)&plo,  g_plo);
    cudaGetSymbolAddress((void**)&whi,  g_whi);
    cudaGetSymbolAddress((void**)&wlo,  g_wlo);

    const int M = (int)NT;
    const long long sc_blocks = ((long long)Tt * Ee * 32 + 255) / 256;
    const dim3 lstm_grid(HID / 32, (Nn + 127) / 128);
    const int init_blocks = (int)(((size_t)Nn * HID + 255) / 256);

    // L1: all weight splits (one launch)
    split_weights_all<<<1024, 256>>>(W1, W2, Wih0, Whh0, Wih1, Whh1, fcn_w, whi, wlo);

    // L2: zero agg
    zero_f4<<<4096, 256>>>((float4*)bufX, NT * (size_t)FIN / 4);

    // L3: agg = spmm(nodes)
    spmm_scatter128<<<(unsigned)sc_blocks, 256>>>(nodes, erow, ecol, ew, bufX, FIN, 0);

    // L4: split agg
    split_rows<<<8192, 256>>>(bufX, ahi, alo, (long long)NT, FIN, FIN, 0);

    // L5: x = relu(agg @ W1 + b1) -> split
    gemm_sp(ahi, alo, whi + OFF_W1T, wlo + OFF_W1T, bhi, blo, b1, M, FIN, H1C, 1);

    // L6: support2 = x @ W2  <-- ncu capture lands here (-s 5 -c 1)
    gemm_f32(bhi, blo, whi + OFF_W2T, wlo + OFF_W2T, bufX, nullptr, M, H1C, H2C, 0);

    // seq = [spmm(support2)+b2 | raw]
    init_seq<<<8192, 256>>>(seq, b2, raw, NT * (size_t)DSEQ);
    spmm_scatter128<<<(unsigned)sc_blocks, 256>>>(bufX, erow, ecol, ew, seq, DSEQ, 1);

    // xg0 = seq @ Wih0^T + bih0
    split_rows<<<8192, 256>>>(seq, bhi, blo, (long long)NT, DSEQ, DSEQP, 0);
    gemm_f32(bhi, blo, whi + OFF_WIH0, wlo + OFF_WIH0, xg, bih0, M, DSEQP, G4, 0);

    // LSTM layer 0 -> split chain in ahi/alo
    lstm_init_kernel<<<init_blocks, 256>>>(xg, bhh0, cst, ahi, alo);
    for (int t = 1; t < Tt; t++) {
        lstm_step_kernel<<<lstm_grid, 256, SHBYTES>>>(
            ahi + (size_t)(t - 1) * HID, alo + (size_t)(t - 1) * HID,
            whi + OFF_WHH0, wlo + OFF_WHH0, xg, bhh0, cst,
            ahi + (size_t)t * HID, alo + (size_t)t * HID, Nn, t);
    }

    // xg1 = hseq0 @ Wih1^T + bih1
    gemm_f32(ahi, alo, whi + OFF_WIH1, wlo + OFF_WIH1, xg, bih1, M, HID, G4, 0);

    // LSTM layer 1 -> split chain (reused)
    lstm_init_kernel<<<init_blocks, 256>>>(xg, bhh1, cst, ahi, alo);
    for (int t = 1; t < Tt; t++) {
        lstm_step_kernel<<<lstm_grid, 256, SHBYTES>>>(
            ahi + (size_t)(t - 1) * HID, alo + (size_t)(t - 1) * HID,
            whi + OFF_WHH1, wlo + OFF_WHH1, xg, bhh1, cst,
            ahi + (size_t)t * HID, alo + (size_t)t * HID, Nn, t);
    }

    // attention pooling (reads split chain) -> split pooled
    attention_pool<<<Nn, HID>>>(ahi, alo, att_w, att_b, phi, plo);

    // z = relu(pooled @ fcn_w + fcn_b)
    gemm_f32(phi, plo, whi + OFF_FCNT, wlo + OFF_FCNT, z, fcn_b, Nn, HID, 128, 1);

    // out = z @ out_w + out_b
    {
        dim3 grid((OUTC + 63) / 64, (Nn + 63) / 64);
        sgemm_kernel<64, 64, 16, 4, 4><<<grid, 256>>>(z, out_w, out, out_b, Nn, 128, OUTC);
    }
}